// round 14
// baseline (speedup 1.0000x reference)
#include <cuda_runtime.h>
#include <cuda_bf16.h>
#include <math.h>
#include <stdint.h>

#define D_MODEL 1024
#define D_FFN   2048
#define NE      8
#define T_TOKENS 4096
#define NPAIR   8192

// ---------------- scratch (device globals) ----------------------------------
__device__ int   g_cnt[NE];
__device__ int   g_gu_ctr;
__device__ int   g_dn_ctr;
__device__ int   g_pid[NE * NPAIR];
__device__ float g_wt [NE * NPAIR];
__device__ __nv_bfloat16 g_xhi[(size_t)T_TOKENS * D_MODEL];
__device__ __nv_bfloat16 g_xlo[(size_t)T_TOKENS * D_MODEL];
__device__ __nv_bfloat16 g_wghi[(size_t)NE * D_FFN * D_MODEL];
__device__ __nv_bfloat16 g_wglo[(size_t)NE * D_FFN * D_MODEL];
__device__ __nv_bfloat16 g_wuhi[(size_t)NE * D_FFN * D_MODEL];
__device__ __nv_bfloat16 g_wulo[(size_t)NE * D_FFN * D_MODEL];
__device__ __nv_bfloat16 g_wdhi[(size_t)NE * D_MODEL * D_FFN];
__device__ __nv_bfloat16 g_wdlo[(size_t)NE * D_MODEL * D_FFN];
__device__ __nv_bfloat16 g_Hhi[(size_t)NPAIR * D_FFN];
__device__ __nv_bfloat16 g_Hlo[(size_t)NPAIR * D_FFN];
__device__ float g_Y[(size_t)NPAIR * D_MODEL];

// ---------------- portable PTX helpers ---------------------------------------
__device__ __forceinline__ uint32_t smem_u32(const void* p) {
    uint32_t a;
    asm("{ .reg .u64 t; cvta.to.shared.u64 t, %1; cvt.u32.u64 %0, t; }" : "=r"(a) : "l"(p));
    return a;
}
#define CP_ASYNC(dst, src) \
    asm volatile("cp.async.cg.shared.global [%0], [%1], 16;" :: "r"(dst), "l"(src))
#define CP_COMMIT() asm volatile("cp.async.commit_group;" ::: "memory")
#define CP_WAIT(n)  asm volatile("cp.async.wait_group %0;" :: "n"(n) : "memory")

__device__ __forceinline__ uint32_t swz(uint32_t o) { return o ^ ((o >> 3) & 0x70); }

__device__ __forceinline__ void ldsm4(uint32_t r[4], uint32_t addr) {
    asm volatile("ldmatrix.sync.aligned.m8n8.x4.shared.b16 {%0,%1,%2,%3}, [%4];"
                 : "=r"(r[0]), "=r"(r[1]), "=r"(r[2]), "=r"(r[3]) : "r"(addr));
}
__device__ __forceinline__ void mma16816(float* c, const uint32_t a[4],
                                         uint32_t b0, uint32_t b1) {
    asm volatile(
        "mma.sync.aligned.m16n8k16.row.col.f32.bf16.bf16.f32 "
        "{%0,%1,%2,%3}, {%4,%5,%6,%7}, {%8,%9}, {%0,%1,%2,%3};"
        : "+f"(c[0]), "+f"(c[1]), "+f"(c[2]), "+f"(c[3])
        : "r"(a[0]), "r"(a[1]), "r"(a[2]), "r"(a[3]), "r"(b0), "r"(b1));
}

// ---------------- kernel 0: reset counters ----------------------------------
__global__ void zero_cnt_kernel() {
    if (threadIdx.x < NE) g_cnt[threadIdx.x] = 0;
    if (threadIdx.x == NE)     g_gu_ctr = 0;
    if (threadIdx.x == NE + 1) g_dn_ctr = 0;
}

// ---------------- kernel 1: router ------------------------------------------
__global__ __launch_bounds__(256) void router_kernel(const float* __restrict__ x,
                                                     const float* __restrict__ wr) {
    const int t = blockIdx.x;
    const int warp = threadIdx.x >> 5, lane = threadIdx.x & 31;
    __shared__ float logits[NE];
    const float* xr = x + (size_t)t * D_MODEL;
    const float* w  = wr + (size_t)warp * D_MODEL;
    float s = 0.f;
    #pragma unroll 8
    for (int i = lane; i < D_MODEL; i += 32) s += xr[i] * w[i];
    #pragma unroll
    for (int o = 16; o; o >>= 1) s += __shfl_xor_sync(0xffffffffu, s, o);
    if (lane == 0) logits[warp] = s;
    __syncthreads();
    if (threadIdx.x == 0) {
        int i0 = 0; float v0 = logits[0];
        #pragma unroll
        for (int e = 1; e < NE; e++) if (logits[e] > v0) { v0 = logits[e]; i0 = e; }
        int i1 = -1; float v1 = -1e30f;
        #pragma unroll
        for (int e = 0; e < NE; e++)
            if (e != i0 && logits[e] > v1) { v1 = logits[e]; i1 = e; }
        float ex = __expf(v1 - v0);
        float w0 = 1.f / (1.f + ex);
        float w1 = ex  / (1.f + ex);
        int s0 = atomicAdd(&g_cnt[i0], 1);
        g_pid[i0 * NPAIR + s0] = t * 2;     g_wt[i0 * NPAIR + s0] = w0;
        int s1 = atomicAdd(&g_cnt[i1], 1);
        g_pid[i1 * NPAIR + s1] = t * 2 + 1; g_wt[i1 * NPAIR + s1] = w1;
    }
}

// ---------------- single merged hi/lo split, 32B per thread -----------------
#define NX4 (T_TOKENS * D_MODEL / 4)
#define NW4 (NE * D_FFN * D_MODEL / 4)
__global__ __launch_bounds__(256) void split_all_kernel(const float4* __restrict__ x,
                                                        const float4* __restrict__ wg,
                                                        const float4* __restrict__ wu,
                                                        const float4* __restrict__ wd) {
    const int totalp = (NX4 + 3 * NW4) / 2;
    union U8 { __nv_bfloat16 b[8]; uint4 u; };
    for (int p = blockIdx.x * blockDim.x + threadIdx.x; p < totalp;
         p += gridDim.x * blockDim.x) {
        int li = p * 2;
        const float4* src;
        uint4 *h4, *l4;
        if (li < NX4)                { src = x;  h4 = (uint4*)g_xhi;  l4 = (uint4*)g_xlo;  }
        else if ((li -= NX4) < NW4)  { src = wg; h4 = (uint4*)g_wghi; l4 = (uint4*)g_wglo; }
        else if ((li -= NW4) < NW4)  { src = wu; h4 = (uint4*)g_wuhi; l4 = (uint4*)g_wulo; }
        else      { li -= NW4;         src = wd; h4 = (uint4*)g_wdhi; l4 = (uint4*)g_wdlo; }
        float4 v0 = src[li], v1 = src[li + 1];
        float vv[8] = { v0.x, v0.y, v0.z, v0.w, v1.x, v1.y, v1.z, v1.w };
        U8 H, L;
        #pragma unroll
        for (int k = 0; k < 8; ++k) {
            H.b[k] = __float2bfloat16(vv[k]);
            L.b[k] = __float2bfloat16(vv[k] - __bfloat162float(H.b[k]));
        }
        h4[li >> 1] = H.u;
        l4[li >> 1] = L.u;
    }
}

// =============================================================================
// gate+up GEMM, PERSISTENT, 3 CTAs/SM. CTA tile M=128 x N=32 (gate AND up).
// K-chunk 32, 3 stages of 24KB: A@0 (16K), Bg@16384 (4K), Bu@20480 (4K).
// 8 warps: wm = wid>>1 (m32), wn = wid&1 (n16). Warp tile 32x16 (g and u).
// acc = 32 floats/thread -> fits 84-reg budget for occupancy 3.
// =============================================================================
#define GU_STAGE 24576
#define GU_SMEM (1024 + 3 * GU_STAGE)
__global__ __launch_bounds__(256, 3) void gateup_kernel() {
    extern __shared__ __align__(1024) char smem[];
    const uint32_t sb = smem_u32(smem);
    int* s_pid = (int*)smem;
    int* s_off = (int*)(smem + 512);
    int* s_idx = (int*)(smem + 552);
    const int tid  = threadIdx.x;
    const int wid  = tid >> 5, lane = tid & 31;
    const int wm   = wid >> 1, wn = wid & 1;

    if (tid == 0) {
        int acc = 0;
        s_off[0] = 0;
        #pragma unroll
        for (int e2 = 0; e2 < NE; ++e2) {
            acc += ((g_cnt[e2] + 127) >> 7) * (D_FFN / 32);
            s_off[e2 + 1] = acc;
        }
    }

    // cp.async store offsets (tile-invariant)
    const int rowA = tid >> 1, sa = (tid & 1) * 2;    // A: 2 thr/row, 2+2 segs
    const int rowB = tid >> 3, c8 = tid & 7;          // B: 8 thr/row, 1 seg each
    uint32_t dAh[2], dAl[2];
    #pragma unroll
    for (int j = 0; j < 2; ++j) {
        dAh[j] = swz((uint32_t)(rowA * 128 + (sa + j) * 16));
        dAl[j] = swz((uint32_t)(rowA * 128 + 64 + (sa + j) * 16));
    }
    const uint32_t dBg = swz((uint32_t)(16384 + rowB * 128 + c8 * 16));
    const uint32_t dBu = dBg + 4096;                  // bit12: swizzle-transparent
    const bool bhi  = (c8 < 4);
    const int  bcol = (c8 & 3) * 8;                   // element col within chunk

    // hoisted ldsm offsets: s=0, hi-half
    const uint32_t klane = (uint32_t)((lane >> 4) * 16);
    uint32_t aofs[2];
    #pragma unroll
    for (int i = 0; i < 2; ++i)
        aofs[i] = swz((uint32_t)((wm * 32 + i * 16 + (lane & 15)) * 128 + klane));
    const uint32_t bofs = swz((uint32_t)(16384 + (wn * 16 + (lane & 15)) * 128 + klane));

    __syncthreads();
    const int total = s_off[NE];

    while (true) {
        __syncthreads();
        if (tid == 0) *s_idx = atomicAdd(&g_gu_ctr, 1);
        __syncthreads();
        const int idx = *s_idx;
        if (idx >= total) break;
        int e = 0;
        while (idx >= s_off[e + 1]) ++e;
        const int local = idx - s_off[e];
        const int mb = local >> 6, nb = local & 63;
        const int ne = g_cnt[e];
        const int m0 = mb * 128, n0 = nb * 32;

        if (tid < 128) {
            int r = m0 + tid;
            s_pid[tid] = g_pid[e * NPAIR + (r < ne ? r : m0)];
        }
        __syncthreads();

        const __nv_bfloat16* gxh = g_xhi + (size_t)(s_pid[rowA] >> 1) * D_MODEL + sa * 8;
        const __nv_bfloat16* gxl = g_xlo + (size_t)(s_pid[rowA] >> 1) * D_MODEL + sa * 8;
        const size_t boff = ((size_t)e * D_FFN + n0 + rowB) * D_MODEL + bcol;
        const __nv_bfloat16* gbg = (bhi ? g_wghi : g_wglo) + boff;
        const __nv_bfloat16* gbu = (bhi ? g_wuhi : g_wulo) + boff;

#define GU_LOAD(kb, st) do {                                                    \
        const uint32_t db = sb + 1024 + (st) * GU_STAGE;                        \
        _Pragma("unroll") for (int j = 0; j < 2; ++j) {                         \
            CP_ASYNC(db + dAh[j], gxh + (kb) + j * 8);                          \
            CP_ASYNC(db + dAl[j], gxl + (kb) + j * 8);                          \
        }                                                                       \
        CP_ASYNC(db + dBg, gbg + (kb));                                         \
        CP_ASYNC(db + dBu, gbu + (kb)); } while (0)

        float ag[2][2][4], au[2][2][4];
        #pragma unroll
        for (int i = 0; i < 2; ++i)
            #pragma unroll
            for (int j = 0; j < 2; ++j)
                #pragma unroll
                for (int q = 0; q < 4; ++q) { ag[i][j][q] = 0.f; au[i][j][q] = 0.f; }

        const int NC = D_MODEL / 32;   // 32 chunks
        GU_LOAD(0, 0);  CP_COMMIT();
        GU_LOAD(32, 1); CP_COMMIT();
        for (int ch = 0; ch < NC; ++ch) {
            if (ch == NC - 1) CP_WAIT(0); else CP_WAIT(1);
            __syncthreads();
            if (ch + 2 < NC) { GU_LOAD((ch + 2) * 32, (ch + 2) % 3); CP_COMMIT(); }
            const uint32_t base = sb + 1024 + (ch % 3) * GU_STAGE;
            #pragma unroll
            for (int s = 0; s < 2; ++s) {
                const uint32_t sd = (uint32_t)(s * 32);
                uint32_t ah[2][4], al[2][4];
                #pragma unroll
                for (int i = 0; i < 2; ++i) {
                    ldsm4(ah[i], base + (aofs[i] ^ sd));
                    ldsm4(al[i], base + (aofs[i] ^ (sd | 64u)));
                }
                uint32_t b[4];
                // gate hi: ah pass then al pass
                ldsm4(b, base + (bofs ^ sd));
                #pragma unroll
                for (int i = 0; i < 2; ++i)
                    #pragma unroll
                    for (int h = 0; h < 2; ++h)
                        mma16816(ag[i][h], ah[i], b[h], b[h + 2]);
                #pragma unroll
                for (int i = 0; i < 2; ++i)
                    #pragma unroll
                    for (int h = 0; h < 2; ++h)
                        mma16816(ag[i][h], al[i], b[h], b[h + 2]);
                // gate lo: ah pass
                ldsm4(b, base + (bofs ^ (sd | 64u)));
                #pragma unroll
                for (int i = 0; i < 2; ++i)
                    #pragma unroll
                    for (int h = 0; h < 2; ++h)
                        mma16816(ag[i][h], ah[i], b[h], b[h + 2]);
                // up hi: ah pass then al pass
                ldsm4(b, base + (bofs ^ (sd | 4096u)));
                #pragma unroll
                for (int i = 0; i < 2; ++i)
                    #pragma unroll
                    for (int h = 0; h < 2; ++h)
                        mma16816(au[i][h], ah[i], b[h], b[h + 2]);
                #pragma unroll
                for (int i = 0; i < 2; ++i)
                    #pragma unroll
                    for (int h = 0; h < 2; ++h)
                        mma16816(au[i][h], al[i], b[h], b[h + 2]);
                // up lo: ah pass
                ldsm4(b, base + (bofs ^ (sd | 4096u | 64u)));
                #pragma unroll
                for (int i = 0; i < 2; ++i)
                    #pragma unroll
                    for (int h = 0; h < 2; ++h)
                        mma16816(au[i][h], ah[i], b[h], b[h + 2]);
            }
        }
#undef GU_LOAD

        // epilogue: SwiGLU, write H hi/lo
        #pragma unroll
        for (int i = 0; i < 2; ++i) {
            const int m1 = wm * 32 + i * 16 + (lane >> 2);
            const int m2 = m1 + 8;
            const int pid1 = s_pid[m1], pid2 = s_pid[m2];
            #pragma unroll
            for (int jh = 0; jh < 2; ++jh) {
                const int col = n0 + wn * 16 + jh * 8 + (lane & 3) * 2;
                const float* cg = ag[i][jh];
                const float* cu = au[i][jh];
                float h0 = (cg[0] / (1.f + __expf(-cg[0]))) * cu[0];
                float h1 = (cg[1] / (1.f + __expf(-cg[1]))) * cu[1];
                float h2 = (cg[2] / (1.f + __expf(-cg[2]))) * cu[2];
                float h3 = (cg[3] / (1.f + __expf(-cg[3]))) * cu[3];
                __nv_bfloat16 a0 = __float2bfloat16(h0), a1 = __float2bfloat16(h1);
                __nv_bfloat16 b0 = __float2bfloat16(h2), b1 = __float2bfloat16(h3);
                __nv_bfloat16 a0l = __float2bfloat16(h0 - __bfloat162float(a0));
                __nv_bfloat16 a1l = __float2bfloat16(h1 - __bfloat162float(a1));
                __nv_bfloat16 b0l = __float2bfloat16(h2 - __bfloat162float(b0));
                __nv_bfloat16 b1l = __float2bfloat16(h3 - __bfloat162float(b1));
                *(__nv_bfloat162*)&g_Hhi[(size_t)pid1 * D_FFN + col] = __nv_bfloat162(a0, a1);
                *(__nv_bfloat162*)&g_Hlo[(size_t)pid1 * D_FFN + col] = __nv_bfloat162(a0l, a1l);
                *(__nv_bfloat162*)&g_Hhi[(size_t)pid2 * D_FFN + col] = __nv_bfloat162(b0, b1);
                *(__nv_bfloat162*)&g_Hlo[(size_t)pid2 * D_FFN + col] = __nv_bfloat162(b0l, b1l);
            }
        }
    }
}

// =============================================================================
// down GEMM, PERSISTENT (unchanged R13 form, 2 CTAs/SM).
// =============================================================================
#define DN_SMEM (2048 + 3 * 32768)
__global__ __launch_bounds__(256, 2) void down_kernel() {
    extern __shared__ __align__(1024) char smem[];
    const uint32_t sb = smem_u32(smem);
    int*   s_pid = (int*)smem;
    float* s_w   = (float*)(smem + 512);
    int*   s_off = (int*)(smem + 1024);
    int*   s_idx = (int*)(smem + 1064);
    const int tid  = threadIdx.x;
    const int wid  = tid >> 5, lane = tid & 31;
    const int wm   = wid >> 2, wn = wid & 3;

    if (tid == 0) {
        int acc = 0;
        s_off[0] = 0;
        #pragma unroll
        for (int e2 = 0; e2 < NE; ++e2) {
            acc += ((g_cnt[e2] + 127) >> 7) * (D_MODEL / 128);
            s_off[e2 + 1] = acc;
        }
    }

    const int rowA = tid >> 1, sa = (tid & 1) * 2;
    uint32_t dAh[2], dAl[2], dBh[2], dBl[2];
    #pragma unroll
    for (int j = 0; j < 2; ++j) {
        dAh[j] = swz((uint32_t)(rowA * 128 + (sa + j) * 16));
        dAl[j] = swz((uint32_t)(rowA * 128 + 64 + (sa + j) * 16));
        dBh[j] = swz((uint32_t)(16384 + rowA * 128 + (sa + j) * 16));
        dBl[j] = swz((uint32_t)(16384 + rowA * 128 + 64 + (sa + j) * 16));
    }

    const uint32_t klane = (uint32_t)((lane >> 4) * 16);
    uint32_t aofs[4], bofs[2];
    #pragma unroll
    for (int i = 0; i < 4; ++i)
        aofs[i] = swz((uint32_t)((wm * 64 + i * 16 + (lane & 15)) * 128 + klane));
    #pragma unroll
    for (int j = 0; j < 2; ++j)
        bofs[j] = swz((uint32_t)(16384 + (wn * 32 + j * 16 + (lane & 15)) * 128 + klane));

    __syncthreads();
    const int total = s_off[NE];

    while (true) {
        __syncthreads();
        if (tid == 0) *s_idx = atomicAdd(&g_dn_ctr, 1);
        __syncthreads();
        const int idx = *s_idx;
        if (idx >= total) break;
        int e = 0;
        while (idx >= s_off[e + 1]) ++e;
        const int local = idx - s_off[e];
        const int mb = local >> 3, nb = local & 7;
        const int ne = g_cnt[e];
        const int m0 = mb * 128, n0 = nb * 128;

        if (tid < 128) {
            int r  = m0 + tid;
            int rr = (r < ne) ? r : m0;
            s_pid[tid] = g_pid[e * NPAIR + rr];
            s_w[tid]   = g_wt [e * NPAIR + rr];
        }
        __syncthreads();

        const __nv_bfloat16* gah = g_Hhi + (size_t)s_pid[rowA] * D_FFN + sa * 8;
        const __nv_bfloat16* gal = g_Hlo + (size_t)s_pid[rowA] * D_FFN + sa * 8;
        const size_t boff = ((size_t)e * D_MODEL + n0 + rowA) * D_FFN + sa * 8;
        const __nv_bfloat16* gbh = g_wdhi + boff;
        const __nv_bfloat16* gbl = g_wdlo + boff;

#define DN_LOAD(kb, st) do {                                                    \
        const uint32_t db = sb + 2048 + (st) * 32768;                           \
        _Pragma("unroll") for (int j = 0; j < 2; ++j) {                         \
            CP_ASYNC(db + dAh[j], gah + (kb) + j * 8);                          \
            CP_ASYNC(db + dAl[j], gal + (kb) + j * 8);                          \
            CP_ASYNC(db + dBh[j], gbh + (kb) + j * 8);                          \
            CP_ASYNC(db + dBl[j], gbl + (kb) + j * 8);                          \
        } } while (0)

        float acc[4][4][4];
        #pragma unroll
        for (int i = 0; i < 4; ++i)
            #pragma unroll
            for (int j = 0; j < 4; ++j)
                #pragma unroll
                for (int q = 0; q < 4; ++q) acc[i][j][q] = 0.f;

        const int NC = D_FFN / 32;   // 64 chunks
        DN_LOAD(0, 0);  CP_COMMIT();
        DN_LOAD(32, 1); CP_COMMIT();
        for (int ch = 0; ch < NC; ++ch) {
            if (ch == NC - 1) CP_WAIT(0); else CP_WAIT(1);
            __syncthreads();
            if (ch + 2 < NC) { DN_LOAD((ch + 2) * 32, (ch + 2) % 3); CP_COMMIT(); }
            const uint32_t base = sb + 2048 + (ch % 3) * 32768;
            #pragma unroll
            for (int s = 0; s < 2; ++s) {
                const uint32_t sd = (uint32_t)(s * 32);
                uint32_t ah[4][4], al[4][4];
                #pragma unroll
                for (int i = 0; i < 4; ++i) {
                    ldsm4(ah[i], base + (aofs[i] ^ sd));
                    ldsm4(al[i], base + (aofs[i] ^ (sd | 64u)));
                }
                uint32_t bh[2][4], bl[2][4];
                ldsm4(bh[0], base + (bofs[0] ^ sd));
                ldsm4(bh[1], base + (bofs[1] ^ sd));
                ldsm4(bl[0], base + (bofs[0] ^ (sd | 64u)));
                ldsm4(bl[1], base + (bofs[1] ^ (sd | 64u)));
                #pragma unroll
                for (int i = 0; i < 4; ++i)
                    #pragma unroll
                    for (int j = 0; j < 2; ++j)
                        #pragma unroll
                        for (int h = 0; h < 2; ++h)
                            mma16816(acc[i][j * 2 + h], ah[i], bh[j][h], bh[j][h + 2]);
                #pragma unroll
                for (int i = 0; i < 4; ++i)
                    #pragma unroll
                    for (int j = 0; j < 2; ++j)
                        #pragma unroll
                        for (int h = 0; h < 2; ++h)
                            mma16816(acc[i][j * 2 + h], al[i], bh[j][h], bh[j][h + 2]);
                #pragma unroll
                for (int i = 0; i < 4; ++i)
                    #pragma unroll
                    for (int j = 0; j < 2; ++j)
                        #pragma unroll
                        for (int h = 0; h < 2; ++h)
                            mma16816(acc[i][j * 2 + h], ah[i], bl[j][h], bl[j][h + 2]);
            }
        }
#undef DN_LOAD

        #pragma unroll
        for (int i = 0; i < 4; ++i) {
            const int m1 = wm * 64 + i * 16 + (lane >> 2);
            const int m2 = m1 + 8;
            const int pid1 = s_pid[m1], pid2 = s_pid[m2];
            const float w1 = s_w[m1], w2 = s_w[m2];
            #pragma unroll
            for (int jn = 0; jn < 4; ++jn) {
                const int col = n0 + wn * 32 + jn * 8 + (lane & 3) * 2;
                const float* c = acc[i][jn];
                float2 v1 = { c[0] * w1, c[1] * w1 };
                float2 v2 = { c[2] * w2, c[3] * w2 };
                *(float2*)&g_Y[(size_t)pid1 * D_MODEL + col] = v1;
                *(float2*)&g_Y[(size_t)pid2 * D_MODEL + col] = v2;
            }
        }
    }
}

// ---------------- kernel: combine pairs + LayerNorm --------------------------
__global__ __launch_bounds__(256) void combine_ln_kernel(const float* __restrict__ gamma,
                                                         const float* __restrict__ beta,
                                                         float* __restrict__ out) {
    const int t   = blockIdx.x;
    const int tid = threadIdx.x;
    const float4 a = ((const float4*)(g_Y + (size_t)(2 * t)     * D_MODEL))[tid];
    const float4 b = ((const float4*)(g_Y + (size_t)(2 * t + 1) * D_MODEL))[tid];
    float4 v = { a.x + b.x, a.y + b.y, a.z + b.z, a.w + b.w };

    float s  = v.x + v.y + v.z + v.w;
    float sq = v.x * v.x + v.y * v.y + v.z * v.z + v.w * v.w;
    #pragma unroll
    for (int o = 16; o; o >>= 1) {
        s  += __shfl_xor_sync(0xffffffffu, s,  o);
        sq += __shfl_xor_sync(0xffffffffu, sq, o);
    }
    __shared__ float rs_[8], rq_[8];
    __shared__ float s_mu, s_rs;
    if ((tid & 31) == 0) { rs_[tid >> 5] = s; rq_[tid >> 5] = sq; }
    __syncthreads();
    if (tid == 0) {
        float S = 0.f, Q = 0.f;
        #pragma unroll
        for (int i = 0; i < 8; i++) { S += rs_[i]; Q += rq_[i]; }
        float mu  = S / (float)D_MODEL;
        float var = Q / (float)D_MODEL - mu * mu;
        s_mu = mu;
        s_rs = rsqrtf(var + 1e-5f);
    }
    __syncthreads();
    const float mu = s_mu, rs = s_rs;
    const float4 gg = ((const float4*)gamma)[tid];
    const float4 bb = ((const float4*)beta)[tid];
    float4 o;
    o.x = (v.x - mu) * rs * gg.x + bb.x;
    o.y = (v.y - mu) * rs * gg.y + bb.y;
    o.z = (v.z - mu) * rs * gg.z + bb.z;
    o.w = (v.w - mu) * rs * gg.w + bb.w;
    ((float4*)out)[(size_t)t * (D_MODEL / 4) + tid] = o;
}

// ---------------- launch ------------------------------------------------------
extern "C" void kernel_launch(void* const* d_in, const int* in_sizes, int n_in,
                              void* d_out, int out_size) {
    const float* x     = (const float*)d_in[0];
    const float* wr    = (const float*)d_in[1];
    const float* wg    = (const float*)d_in[2];
    const float* wu    = (const float*)d_in[3];
    const float* wd    = (const float*)d_in[4];
    const float* gamma = (const float*)d_in[5];
    const float* beta  = (const float*)d_in[6];
    float* out = (float*)d_out;

    cudaFuncSetAttribute(gateup_kernel, cudaFuncAttributeMaxDynamicSharedMemorySize, GU_SMEM);
    cudaFuncSetAttribute(down_kernel,   cudaFuncAttributeMaxDynamicSharedMemorySize, DN_SMEM);

    zero_cnt_kernel<<<1, 32>>>();
    router_kernel<<<T_TOKENS, 256>>>(x, wr);
    split_all_kernel<<<6656, 256>>>((const float4*)x, (const float4*)wg,
                                    (const float4*)wu, (const float4*)wd);
    gateup_kernel<<<444, 256, GU_SMEM>>>();
    down_kernel<<<304, 256, DN_SMEM>>>();
    combine_ln_kernel<<<T_TOKENS, 256>>>(gamma, beta, out);
}

// round 15
// speedup vs baseline: 1.1001x; 1.1001x over previous
#include <cuda_runtime.h>
#include <cuda_bf16.h>
#include <math.h>
#include <stdint.h>

#define D_MODEL 1024
#define D_FFN   2048
#define NE      8
#define T_TOKENS 4096
#define NPAIR   8192

// ---------------- scratch (device globals) ----------------------------------
__device__ int   g_cnt[NE];
__device__ int   g_ctr;
__device__ int   g_ready[NE * 64];   // per (expert, m-block) completed gateup n-tiles
__device__ int   g_pid[NE * NPAIR];
__device__ float g_wt [NE * NPAIR];
__device__ __nv_bfloat16 g_xhi[(size_t)T_TOKENS * D_MODEL];
__device__ __nv_bfloat16 g_xlo[(size_t)T_TOKENS * D_MODEL];
__device__ __nv_bfloat16 g_wghi[(size_t)NE * D_FFN * D_MODEL];
__device__ __nv_bfloat16 g_wglo[(size_t)NE * D_FFN * D_MODEL];
__device__ __nv_bfloat16 g_wuhi[(size_t)NE * D_FFN * D_MODEL];
__device__ __nv_bfloat16 g_wulo[(size_t)NE * D_FFN * D_MODEL];
__device__ __nv_bfloat16 g_wdhi[(size_t)NE * D_MODEL * D_FFN];
__device__ __nv_bfloat16 g_wdlo[(size_t)NE * D_MODEL * D_FFN];
__device__ __nv_bfloat16 g_Hhi[(size_t)NPAIR * D_FFN];
__device__ __nv_bfloat16 g_Hlo[(size_t)NPAIR * D_FFN];
__device__ float g_Y[(size_t)NPAIR * D_MODEL];

// ---------------- portable PTX helpers ---------------------------------------
__device__ __forceinline__ uint32_t smem_u32(const void* p) {
    uint32_t a;
    asm("{ .reg .u64 t; cvta.to.shared.u64 t, %1; cvt.u32.u64 %0, t; }" : "=r"(a) : "l"(p));
    return a;
}
#define CP_ASYNC(dst, src) \
    asm volatile("cp.async.cg.shared.global [%0], [%1], 16;" :: "r"(dst), "l"(src))
#define CP_COMMIT() asm volatile("cp.async.commit_group;" ::: "memory")
#define CP_WAIT(n)  asm volatile("cp.async.wait_group %0;" :: "n"(n) : "memory")

__device__ __forceinline__ uint32_t swz(uint32_t o) { return o ^ ((o >> 3) & 0x70); }

__device__ __forceinline__ void ldsm4(uint32_t r[4], uint32_t addr) {
    asm volatile("ldmatrix.sync.aligned.m8n8.x4.shared.b16 {%0,%1,%2,%3}, [%4];"
                 : "=r"(r[0]), "=r"(r[1]), "=r"(r[2]), "=r"(r[3]) : "r"(addr));
}
__device__ __forceinline__ void mma16816(float* c, const uint32_t a[4],
                                         uint32_t b0, uint32_t b1) {
    asm volatile(
        "mma.sync.aligned.m16n8k16.row.col.f32.bf16.bf16.f32 "
        "{%0,%1,%2,%3}, {%4,%5,%6,%7}, {%8,%9}, {%0,%1,%2,%3};"
        : "+f"(c[0]), "+f"(c[1]), "+f"(c[2]), "+f"(c[3])
        : "r"(a[0]), "r"(a[1]), "r"(a[2]), "r"(a[3]), "r"(b0), "r"(b1));
}

// ---------------- kernel 0: reset counters ----------------------------------
__global__ __launch_bounds__(512) void zero_cnt_kernel() {
    const int t = threadIdx.x;
    if (t < NE) g_cnt[t] = 0;
    if (t == NE) g_ctr = 0;
    if (t < NE * 64) g_ready[t] = 0;
}

// ---------------- kernel 1: router ------------------------------------------
__global__ __launch_bounds__(256) void router_kernel(const float* __restrict__ x,
                                                     const float* __restrict__ wr) {
    const int t = blockIdx.x;
    const int warp = threadIdx.x >> 5, lane = threadIdx.x & 31;
    __shared__ float logits[NE];
    const float* xr = x + (size_t)t * D_MODEL;
    const float* w  = wr + (size_t)warp * D_MODEL;
    float s = 0.f;
    #pragma unroll 8
    for (int i = lane; i < D_MODEL; i += 32) s += xr[i] * w[i];
    #pragma unroll
    for (int o = 16; o; o >>= 1) s += __shfl_xor_sync(0xffffffffu, s, o);
    if (lane == 0) logits[warp] = s;
    __syncthreads();
    if (threadIdx.x == 0) {
        int i0 = 0; float v0 = logits[0];
        #pragma unroll
        for (int e = 1; e < NE; e++) if (logits[e] > v0) { v0 = logits[e]; i0 = e; }
        int i1 = -1; float v1 = -1e30f;
        #pragma unroll
        for (int e = 0; e < NE; e++)
            if (e != i0 && logits[e] > v1) { v1 = logits[e]; i1 = e; }
        float ex = __expf(v1 - v0);
        float w0 = 1.f / (1.f + ex);
        float w1 = ex  / (1.f + ex);
        int s0 = atomicAdd(&g_cnt[i0], 1);
        g_pid[i0 * NPAIR + s0] = t * 2;     g_wt[i0 * NPAIR + s0] = w0;
        int s1 = atomicAdd(&g_cnt[i1], 1);
        g_pid[i1 * NPAIR + s1] = t * 2 + 1; g_wt[i1 * NPAIR + s1] = w1;
    }
}

// ---------------- single merged hi/lo split, 32B per thread -----------------
#define NX4 (T_TOKENS * D_MODEL / 4)
#define NW4 (NE * D_FFN * D_MODEL / 4)
__global__ __launch_bounds__(256) void split_all_kernel(const float4* __restrict__ x,
                                                        const float4* __restrict__ wg,
                                                        const float4* __restrict__ wu,
                                                        const float4* __restrict__ wd) {
    const int totalp = (NX4 + 3 * NW4) / 2;
    union U8 { __nv_bfloat16 b[8]; uint4 u; };
    for (int p = blockIdx.x * blockDim.x + threadIdx.x; p < totalp;
         p += gridDim.x * blockDim.x) {
        int li = p * 2;
        const float4* src;
        uint4 *h4, *l4;
        if (li < NX4)                { src = x;  h4 = (uint4*)g_xhi;  l4 = (uint4*)g_xlo;  }
        else if ((li -= NX4) < NW4)  { src = wg; h4 = (uint4*)g_wghi; l4 = (uint4*)g_wglo; }
        else if ((li -= NW4) < NW4)  { src = wu; h4 = (uint4*)g_wuhi; l4 = (uint4*)g_wulo; }
        else      { li -= NW4;         src = wd; h4 = (uint4*)g_wdhi; l4 = (uint4*)g_wdlo; }
        float4 v0 = src[li], v1 = src[li + 1];
        float vv[8] = { v0.x, v0.y, v0.z, v0.w, v1.x, v1.y, v1.z, v1.w };
        U8 H, L;
        #pragma unroll
        for (int k = 0; k < 8; ++k) {
            H.b[k] = __float2bfloat16(vv[k]);
            L.b[k] = __float2bfloat16(vv[k] - __bfloat162float(H.b[k]));
        }
        h4[li >> 1] = H.u;
        l4[li >> 1] = L.u;
    }
}

// =============================================================================
// FUSED persistent MoE GEMM kernel: gateup tasks first, down tasks after,
// one atomic work counter; down tiles wait on per-(e,mb) readiness (=32).
// smem: s_pid[128]@0, s_w[128]@512, s_offg[9]@1024, s_offd[9]@1060,
//       s_idx@1100, stage data @2048 (3 x 32768).
// =============================================================================
#define FU_SMEM (2048 + 3 * 32768)
__global__ __launch_bounds__(256, 2) void moe_fused_kernel() {
    extern __shared__ __align__(1024) char smem[];
    const uint32_t sb = smem_u32(smem);
    int*   s_pid  = (int*)smem;
    float* s_w    = (float*)(smem + 512);
    int*   s_offg = (int*)(smem + 1024);
    int*   s_offd = (int*)(smem + 1060);
    int*   s_idx  = (int*)(smem + 1100);
    const int tid  = threadIdx.x;
    const int wid  = tid >> 5, lane = tid & 31;

    if (tid == 0) {
        int ag = 0, ad = 0;
        s_offg[0] = 0; s_offd[0] = 0;
        #pragma unroll
        for (int e2 = 0; e2 < NE; ++e2) {
            const int mbc = (g_cnt[e2] + 127) >> 7;
            ag += mbc * (D_FFN / 64);
            ad += mbc * (D_MODEL / 128);
            s_offg[e2 + 1] = ag;
            s_offd[e2 + 1] = ad;
        }
    }
    // shared cp.async A-row geometry (both phases)
    const int rowA = tid >> 1, sa = (tid & 1) * 2;
    uint32_t dAh[2], dAl[2];
    #pragma unroll
    for (int j = 0; j < 2; ++j) {
        dAh[j] = swz((uint32_t)(rowA * 128 + (sa + j) * 16));
        dAl[j] = swz((uint32_t)(rowA * 128 + 64 + (sa + j) * 16));
    }
    const uint32_t klane = (uint32_t)((lane >> 4) * 16);
    __syncthreads();
    const int totalg = s_offg[NE];
    const int totald = s_offd[NE];

    while (true) {
        __syncthreads();   // protects s_pid/s_w reuse
        if (tid == 0) *s_idx = atomicAdd(&g_ctr, 1);
        __syncthreads();
        const int idx = *s_idx;
        if (idx >= totalg + totald) break;

        if (idx < totalg) {
            // ================= GATEUP TILE (R13 body) =================
            const int wm = wid >> 1, wn = wid & 1;
            int e = 0;
            while (idx >= s_offg[e + 1]) ++e;
            const int local = idx - s_offg[e];
            const int mb = local >> 5, nb = local & 31;
            const int ne = g_cnt[e];
            const int m0 = mb * 128, n0 = nb * 64;

            if (tid < 128) {
                int r = m0 + tid;
                s_pid[tid] = g_pid[e * NPAIR + (r < ne ? r : m0)];
            }
            __syncthreads();

            const int rowB = tid >> 2, sgB = tid & 3;
            const uint32_t dBgh = swz((uint32_t)(16384 + rowB * 128 + sgB * 16));
            const uint32_t dBgl = swz((uint32_t)(16384 + rowB * 128 + 64 + sgB * 16));
            const uint32_t dBuh = swz((uint32_t)(24576 + rowB * 128 + sgB * 16));
            const uint32_t dBul = swz((uint32_t)(24576 + rowB * 128 + 64 + sgB * 16));
            uint32_t aofs[2], bofs[2];
            #pragma unroll
            for (int i = 0; i < 2; ++i)
                aofs[i] = swz((uint32_t)((wm * 32 + i * 16 + (lane & 15)) * 128 + klane));
            #pragma unroll
            for (int j = 0; j < 2; ++j)
                bofs[j] = swz((uint32_t)(16384 + (wn * 32 + j * 16 + (lane & 15)) * 128 + klane));

            const __nv_bfloat16* gxh = g_xhi + (size_t)(s_pid[rowA] >> 1) * D_MODEL + sa * 8;
            const __nv_bfloat16* gxl = g_xlo + (size_t)(s_pid[rowA] >> 1) * D_MODEL + sa * 8;
            const size_t boff = ((size_t)e * D_FFN + n0 + rowB) * D_MODEL + sgB * 8;
            const __nv_bfloat16* gbgh = g_wghi + boff;
            const __nv_bfloat16* gbgl = g_wglo + boff;
            const __nv_bfloat16* gbuh = g_wuhi + boff;
            const __nv_bfloat16* gbul = g_wulo + boff;

#define GU_LOAD(kb, st) do {                                                    \
        const uint32_t db = sb + 2048 + (st) * 32768;                           \
        _Pragma("unroll") for (int j = 0; j < 2; ++j) {                         \
            CP_ASYNC(db + dAh[j], gxh + (kb) + j * 8);                          \
            CP_ASYNC(db + dAl[j], gxl + (kb) + j * 8);                          \
        }                                                                       \
        CP_ASYNC(db + dBgh, gbgh + (kb));                                       \
        CP_ASYNC(db + dBgl, gbgl + (kb));                                       \
        CP_ASYNC(db + dBuh, gbuh + (kb));                                       \
        CP_ASYNC(db + dBul, gbul + (kb)); } while (0)

            float ag[2][4][4], au[2][4][4];
            #pragma unroll
            for (int i = 0; i < 2; ++i)
                #pragma unroll
                for (int j = 0; j < 4; ++j)
                    #pragma unroll
                    for (int q = 0; q < 4; ++q) { ag[i][j][q] = 0.f; au[i][j][q] = 0.f; }

            const int NC = D_MODEL / 32;
            GU_LOAD(0, 0);  CP_COMMIT();
            GU_LOAD(32, 1); CP_COMMIT();
            for (int ch = 0; ch < NC; ++ch) {
                if (ch == NC - 1) CP_WAIT(0); else CP_WAIT(1);
                __syncthreads();
                if (ch + 2 < NC) { GU_LOAD((ch + 2) * 32, (ch + 2) % 3); CP_COMMIT(); }
                const uint32_t base = sb + 2048 + (ch % 3) * 32768;
                #pragma unroll
                for (int s = 0; s < 2; ++s) {
                    const uint32_t sd = (uint32_t)(s * 32);
                    uint32_t ah[2][4], al[2][4];
                    #pragma unroll
                    for (int i = 0; i < 2; ++i) {
                        ldsm4(ah[i], base + (aofs[i] ^ sd));
                        ldsm4(al[i], base + (aofs[i] ^ (sd | 64u)));
                    }
                    {   // gate hi
                        uint32_t b[2][4];
                        ldsm4(b[0], base + (bofs[0] ^ sd));
                        ldsm4(b[1], base + (bofs[1] ^ sd));
                        #pragma unroll
                        for (int i = 0; i < 2; ++i)
                            #pragma unroll
                            for (int j = 0; j < 2; ++j)
                                #pragma unroll
                                for (int h = 0; h < 2; ++h)
                                    mma16816(ag[i][j * 2 + h], ah[i], b[j][h], b[j][h + 2]);
                        #pragma unroll
                        for (int i = 0; i < 2; ++i)
                            #pragma unroll
                            for (int j = 0; j < 2; ++j)
                                #pragma unroll
                                for (int h = 0; h < 2; ++h)
                                    mma16816(ag[i][j * 2 + h], al[i], b[j][h], b[j][h + 2]);
                    }
                    {   // gate lo
                        uint32_t b[2][4];
                        ldsm4(b[0], base + (bofs[0] ^ (sd | 64u)));
                        ldsm4(b[1], base + (bofs[1] ^ (sd | 64u)));
                        #pragma unroll
                        for (int i = 0; i < 2; ++i)
                            #pragma unroll
                            for (int j = 0; j < 2; ++j)
                                #pragma unroll
                                for (int h = 0; h < 2; ++h)
                                    mma16816(ag[i][j * 2 + h], ah[i], b[j][h], b[j][h + 2]);
                    }
                    {   // up hi
                        uint32_t b[2][4];
                        ldsm4(b[0], base + (bofs[0] ^ (sd | 8192u)));
                        ldsm4(b[1], base + (bofs[1] ^ (sd | 8192u)));
                        #pragma unroll
                        for (int i = 0; i < 2; ++i)
                            #pragma unroll
                            for (int j = 0; j < 2; ++j)
                                #pragma unroll
                                for (int h = 0; h < 2; ++h)
                                    mma16816(au[i][j * 2 + h], ah[i], b[j][h], b[j][h + 2]);
                        #pragma unroll
                        for (int i = 0; i < 2; ++i)
                            #pragma unroll
                            for (int j = 0; j < 2; ++j)
                                #pragma unroll
                                for (int h = 0; h < 2; ++h)
                                    mma16816(au[i][j * 2 + h], al[i], b[j][h], b[j][h + 2]);
                    }
                    {   // up lo
                        uint32_t b[2][4];
                        ldsm4(b[0], base + (bofs[0] ^ (sd | 8256u)));
                        ldsm4(b[1], base + (bofs[1] ^ (sd | 8256u)));
                        #pragma unroll
                        for (int i = 0; i < 2; ++i)
                            #pragma unroll
                            for (int j = 0; j < 2; ++j)
                                #pragma unroll
                                for (int h = 0; h < 2; ++h)
                                    mma16816(au[i][j * 2 + h], ah[i], b[j][h], b[j][h + 2]);
                    }
                }
            }
#undef GU_LOAD

            // epilogue: SwiGLU -> H hi/lo
            #pragma unroll
            for (int i = 0; i < 2; ++i) {
                const int m1 = wm * 32 + i * 16 + (lane >> 2);
                const int m2 = m1 + 8;
                const int pid1 = s_pid[m1], pid2 = s_pid[m2];
                #pragma unroll
                for (int jn = 0; jn < 4; ++jn) {
                    const int col = n0 + wn * 32 + jn * 8 + (lane & 3) * 2;
                    const float* cg = ag[i][jn];
                    const float* cu = au[i][jn];
                    float h0 = (cg[0] / (1.f + __expf(-cg[0]))) * cu[0];
                    float h1 = (cg[1] / (1.f + __expf(-cg[1]))) * cu[1];
                    float h2 = (cg[2] / (1.f + __expf(-cg[2]))) * cu[2];
                    float h3 = (cg[3] / (1.f + __expf(-cg[3]))) * cu[3];
                    __nv_bfloat16 a0 = __float2bfloat16(h0), a1 = __float2bfloat16(h1);
                    __nv_bfloat16 b0 = __float2bfloat16(h2), b1 = __float2bfloat16(h3);
                    __nv_bfloat16 a0l = __float2bfloat16(h0 - __bfloat162float(a0));
                    __nv_bfloat16 a1l = __float2bfloat16(h1 - __bfloat162float(a1));
                    __nv_bfloat16 b0l = __float2bfloat16(h2 - __bfloat162float(b0));
                    __nv_bfloat16 b1l = __float2bfloat16(h3 - __bfloat162float(b1));
                    *(__nv_bfloat162*)&g_Hhi[(size_t)pid1 * D_FFN + col] = __nv_bfloat162(a0, a1);
                    *(__nv_bfloat162*)&g_Hlo[(size_t)pid1 * D_FFN + col] = __nv_bfloat162(a0l, a1l);
                    *(__nv_bfloat162*)&g_Hhi[(size_t)pid2 * D_FFN + col] = __nv_bfloat162(b0, b1);
                    *(__nv_bfloat162*)&g_Hlo[(size_t)pid2 * D_FFN + col] = __nv_bfloat162(b0l, b1l);
                }
            }
            // publish: all H writes visible, then signal readiness
            __threadfence();
            __syncthreads();
            if (tid == 0) atomicAdd(&g_ready[e * 64 + mb], 1);
        } else {
            // ================= DOWN TILE (R13 body) =================
            const int didx = idx - totalg;
            const int wm = wid >> 2, wn = wid & 3;
            int e = 0;
            while (didx >= s_offd[e + 1]) ++e;
            const int local = didx - s_offd[e];
            const int mb = local >> 3, nb = local & 7;
            const int ne = g_cnt[e];
            const int m0 = mb * 128, n0 = nb * 128;

            // wait until all 32 gateup n-tiles for (e, mb) have published H
            if (tid == 0) {
                const int* rp = &g_ready[e * 64 + mb];
                int v;
                do {
                    asm volatile("ld.global.acquire.gpu.b32 %0, [%1];" : "=r"(v) : "l"(rp));
                } while (v < 32);
            }
            __syncthreads();

            if (tid < 128) {
                int r  = m0 + tid;
                int rr = (r < ne) ? r : m0;
                s_pid[tid] = g_pid[e * NPAIR + rr];
                s_w[tid]   = g_wt [e * NPAIR + rr];
            }
            __syncthreads();

            const uint32_t dBh0 = swz((uint32_t)(16384 + rowA * 128 + (sa + 0) * 16));
            const uint32_t dBh1 = swz((uint32_t)(16384 + rowA * 128 + (sa + 1) * 16));
            const uint32_t dBl0 = swz((uint32_t)(16384 + rowA * 128 + 64 + (sa + 0) * 16));
            const uint32_t dBl1 = swz((uint32_t)(16384 + rowA * 128 + 64 + (sa + 1) * 16));
            uint32_t aofs[4], bofs[2];
            #pragma unroll
            for (int i = 0; i < 4; ++i)
                aofs[i] = swz((uint32_t)((wm * 64 + i * 16 + (lane & 15)) * 128 + klane));
            #pragma unroll
            for (int j = 0; j < 2; ++j)
                bofs[j] = swz((uint32_t)(16384 + (wn * 32 + j * 16 + (lane & 15)) * 128 + klane));

            const __nv_bfloat16* gah = g_Hhi + (size_t)s_pid[rowA] * D_FFN + sa * 8;
            const __nv_bfloat16* gal = g_Hlo + (size_t)s_pid[rowA] * D_FFN + sa * 8;
            const size_t boff = ((size_t)e * D_MODEL + n0 + rowA) * D_FFN + sa * 8;
            const __nv_bfloat16* gbh = g_wdhi + boff;
            const __nv_bfloat16* gbl = g_wdlo + boff;

#define DN_LOAD(kb, st) do {                                                    \
        const uint32_t db = sb + 2048 + (st) * 32768;                           \
        _Pragma("unroll") for (int j = 0; j < 2; ++j) {                         \
            CP_ASYNC(db + dAh[j], gah + (kb) + j * 8);                          \
            CP_ASYNC(db + dAl[j], gal + (kb) + j * 8);                          \
        }                                                                       \
        CP_ASYNC(db + dBh0, gbh + (kb));                                        \
        CP_ASYNC(db + dBh1, gbh + (kb) + 8);                                    \
        CP_ASYNC(db + dBl0, gbl + (kb));                                        \
        CP_ASYNC(db + dBl1, gbl + (kb) + 8); } while (0)

            float acc[4][4][4];
            #pragma unroll
            for (int i = 0; i < 4; ++i)
                #pragma unroll
                for (int j = 0; j < 4; ++j)
                    #pragma unroll
                    for (int q = 0; q < 4; ++q) acc[i][j][q] = 0.f;

            const int NC = D_FFN / 32;
            DN_LOAD(0, 0);  CP_COMMIT();
            DN_LOAD(32, 1); CP_COMMIT();
            for (int ch = 0; ch < NC; ++ch) {
                if (ch == NC - 1) CP_WAIT(0); else CP_WAIT(1);
                __syncthreads();
                if (ch + 2 < NC) { DN_LOAD((ch + 2) * 32, (ch + 2) % 3); CP_COMMIT(); }
                const uint32_t base = sb + 2048 + (ch % 3) * 32768;
                #pragma unroll
                for (int s = 0; s < 2; ++s) {
                    const uint32_t sd = (uint32_t)(s * 32);
                    uint32_t ah[4][4], al[4][4];
                    #pragma unroll
                    for (int i = 0; i < 4; ++i) {
                        ldsm4(ah[i], base + (aofs[i] ^ sd));
                        ldsm4(al[i], base + (aofs[i] ^ (sd | 64u)));
                    }
                    uint32_t bh[2][4], bl[2][4];
                    ldsm4(bh[0], base + (bofs[0] ^ sd));
                    ldsm4(bh[1], base + (bofs[1] ^ sd));
                    ldsm4(bl[0], base + (bofs[0] ^ (sd | 64u)));
                    ldsm4(bl[1], base + (bofs[1] ^ (sd | 64u)));
                    #pragma unroll
                    for (int i = 0; i < 4; ++i)
                        #pragma unroll
                        for (int j = 0; j < 2; ++j)
                            #pragma unroll
                            for (int h = 0; h < 2; ++h)
                                mma16816(acc[i][j * 2 + h], ah[i], bh[j][h], bh[j][h + 2]);
                    #pragma unroll
                    for (int i = 0; i < 4; ++i)
                        #pragma unroll
                        for (int j = 0; j < 2; ++j)
                            #pragma unroll
                            for (int h = 0; h < 2; ++h)
                                mma16816(acc[i][j * 2 + h], al[i], bh[j][h], bh[j][h + 2]);
                    #pragma unroll
                    for (int i = 0; i < 4; ++i)
                        #pragma unroll
                        for (int j = 0; j < 2; ++j)
                            #pragma unroll
                            for (int h = 0; h < 2; ++h)
                                mma16816(acc[i][j * 2 + h], ah[i], bl[j][h], bl[j][h + 2]);
                }
            }
#undef DN_LOAD

            #pragma unroll
            for (int i = 0; i < 4; ++i) {
                const int m1 = wm * 64 + i * 16 + (lane >> 2);
                const int m2 = m1 + 8;
                const int pid1 = s_pid[m1], pid2 = s_pid[m2];
                const float w1 = s_w[m1], w2 = s_w[m2];
                #pragma unroll
                for (int jn = 0; jn < 4; ++jn) {
                    const int col = n0 + wn * 32 + jn * 8 + (lane & 3) * 2;
                    const float* c = acc[i][jn];
                    float2 v1 = { c[0] * w1, c[1] * w1 };
                    float2 v2 = { c[2] * w2, c[3] * w2 };
                    *(float2*)&g_Y[(size_t)pid1 * D_MODEL + col] = v1;
                    *(float2*)&g_Y[(size_t)pid2 * D_MODEL + col] = v2;
                }
            }
        }
    }
}

// ---------------- kernel: combine pairs + LayerNorm --------------------------
__global__ __launch_bounds__(256) void combine_ln_kernel(const float* __restrict__ gamma,
                                                         const float* __restrict__ beta,
                                                         float* __restrict__ out) {
    const int t   = blockIdx.x;
    const int tid = threadIdx.x;
    const float4 a = ((const float4*)(g_Y + (size_t)(2 * t)     * D_MODEL))[tid];
    const float4 b = ((const float4*)(g_Y + (size_t)(2 * t + 1) * D_MODEL))[tid];
    float4 v = { a.x + b.x, a.y + b.y, a.z + b.z, a.w + b.w };

    float s  = v.x + v.y + v.z + v.w;
    float sq = v.x * v.x + v.y * v.y + v.z * v.z + v.w * v.w;
    #pragma unroll
    for (int o = 16; o; o >>= 1) {
        s  += __shfl_xor_sync(0xffffffffu, s,  o);
        sq += __shfl_xor_sync(0xffffffffu, sq, o);
    }
    __shared__ float rs_[8], rq_[8];
    __shared__ float s_mu, s_rs;
    if ((tid & 31) == 0) { rs_[tid >> 5] = s; rq_[tid >> 5] = sq; }
    __syncthreads();
    if (tid == 0) {
        float S = 0.f, Q = 0.f;
        #pragma unroll
        for (int i = 0; i < 8; i++) { S += rs_[i]; Q += rq_[i]; }
        float mu  = S / (float)D_MODEL;
        float var = Q / (float)D_MODEL - mu * mu;
        s_mu = mu;
        s_rs = rsqrtf(var + 1e-5f);
    }
    __syncthreads();
    const float mu = s_mu, rs = s_rs;
    const float4 gg = ((const float4*)gamma)[tid];
    const float4 bb = ((const float4*)beta)[tid];
    float4 o;
    o.x = (v.x - mu) * rs * gg.x + bb.x;
    o.y = (v.y - mu) * rs * gg.y + bb.y;
    o.z = (v.z - mu) * rs * gg.z + bb.z;
    o.w = (v.w - mu) * rs * gg.w + bb.w;
    ((float4*)out)[(size_t)t * (D_MODEL / 4) + tid] = o;
}

// ---------------- launch ------------------------------------------------------
extern "C" void kernel_launch(void* const* d_in, const int* in_sizes, int n_in,
                              void* d_out, int out_size) {
    const float* x     = (const float*)d_in[0];
    const float* wr    = (const float*)d_in[1];
    const float* wg    = (const float*)d_in[2];
    const float* wu    = (const float*)d_in[3];
    const float* wd    = (const float*)d_in[4];
    const float* gamma = (const float*)d_in[5];
    const float* beta  = (const float*)d_in[6];
    float* out = (float*)d_out;

    cudaFuncSetAttribute(moe_fused_kernel, cudaFuncAttributeMaxDynamicSharedMemorySize, FU_SMEM);

    zero_cnt_kernel<<<1, 512>>>();
    router_kernel<<<T_TOKENS, 256>>>(x, wr);
    split_all_kernel<<<6656, 256>>>((const float4*)x, (const float4*)wg,
                                    (const float4*)wu, (const float4*)wd);
    moe_fused_kernel<<<304, 256, FU_SMEM>>>();
    combine_ln_kernel<<<T_TOKENS, 256>>>(gamma, beta, out);
}

// round 16
// speedup vs baseline: 1.2381x; 1.1254x over previous
#include <cuda_runtime.h>
#include <cuda_bf16.h>
#include <cuda_fp16.h>
#include <math.h>
#include <stdint.h>

#define D_MODEL 1024
#define D_FFN   2048
#define NE      8
#define T_TOKENS 4096
#define NPAIR   8192

// ---------------- scratch (device globals) ----------------------------------
__device__ int   g_cnt[NE];
__device__ int   g_ctr;
__device__ int   g_ready[NE * 64];
__device__ int   g_pid[NE * NPAIR];
__device__ float g_wt [NE * NPAIR];
__device__ __nv_bfloat16 g_xhi[(size_t)T_TOKENS * D_MODEL];
__device__ __nv_bfloat16 g_xlo[(size_t)T_TOKENS * D_MODEL];
__device__ __nv_bfloat16 g_wghi[(size_t)NE * D_FFN * D_MODEL];
__device__ __nv_bfloat16 g_wglo[(size_t)NE * D_FFN * D_MODEL];
__device__ __nv_bfloat16 g_wuhi[(size_t)NE * D_FFN * D_MODEL];
__device__ __nv_bfloat16 g_wulo[(size_t)NE * D_FFN * D_MODEL];
__device__ __half g_wdhi[(size_t)NE * D_MODEL * D_FFN];
__device__ __half g_wdlo[(size_t)NE * D_MODEL * D_FFN];
__device__ __half g_H16[(size_t)NPAIR * D_FFN];
__device__ float g_Y[(size_t)NPAIR * D_MODEL];

// ---------------- portable PTX helpers ---------------------------------------
__device__ __forceinline__ uint32_t smem_u32(const void* p) {
    uint32_t a;
    asm("{ .reg .u64 t; cvta.to.shared.u64 t, %1; cvt.u32.u64 %0, t; }" : "=r"(a) : "l"(p));
    return a;
}
#define CP_ASYNC(dst, src) \
    asm volatile("cp.async.cg.shared.global [%0], [%1], 16;" :: "r"(dst), "l"(src))
#define CP_COMMIT() asm volatile("cp.async.commit_group;" ::: "memory")
#define CP_WAIT(n)  asm volatile("cp.async.wait_group %0;" :: "n"(n) : "memory")

__device__ __forceinline__ uint32_t swz(uint32_t o) { return o ^ ((o >> 3) & 0x70); }

__device__ __forceinline__ void ldsm4(uint32_t r[4], uint32_t addr) {
    asm volatile("ldmatrix.sync.aligned.m8n8.x4.shared.b16 {%0,%1,%2,%3}, [%4];"
                 : "=r"(r[0]), "=r"(r[1]), "=r"(r[2]), "=r"(r[3]) : "r"(addr));
}
__device__ __forceinline__ void mma16816(float* c, const uint32_t a[4],
                                         uint32_t b0, uint32_t b1) {
    asm volatile(
        "mma.sync.aligned.m16n8k16.row.col.f32.bf16.bf16.f32 "
        "{%0,%1,%2,%3}, {%4,%5,%6,%7}, {%8,%9}, {%0,%1,%2,%3};"
        : "+f"(c[0]), "+f"(c[1]), "+f"(c[2]), "+f"(c[3])
        : "r"(a[0]), "r"(a[1]), "r"(a[2]), "r"(a[3]), "r"(b0), "r"(b1));
}
__device__ __forceinline__ void mma16816h(float* c, const uint32_t a[4],
                                          uint32_t b0, uint32_t b1) {
    asm volatile(
        "mma.sync.aligned.m16n8k16.row.col.f32.f16.f16.f32 "
        "{%0,%1,%2,%3}, {%4,%5,%6,%7}, {%8,%9}, {%0,%1,%2,%3};"
        : "+f"(c[0]), "+f"(c[1]), "+f"(c[2]), "+f"(c[3])
        : "r"(a[0]), "r"(a[1]), "r"(a[2]), "r"(a[3]), "r"(b0), "r"(b1));
}

// ---------------- kernel 0: reset counters ----------------------------------
__global__ __launch_bounds__(512) void zero_cnt_kernel() {
    const int t = threadIdx.x;
    if (t < NE) g_cnt[t] = 0;
    if (t == NE) g_ctr = 0;
    if (t < NE * 64) g_ready[t] = 0;
}

// ---------------- kernel 1: router ------------------------------------------
__global__ __launch_bounds__(256) void router_kernel(const float* __restrict__ x,
                                                     const float* __restrict__ wr) {
    const int t = blockIdx.x;
    const int warp = threadIdx.x >> 5, lane = threadIdx.x & 31;
    __shared__ float logits[NE];
    const float* xr = x + (size_t)t * D_MODEL;
    const float* w  = wr + (size_t)warp * D_MODEL;
    float s = 0.f;
    #pragma unroll 8
    for (int i = lane; i < D_MODEL; i += 32) s += xr[i] * w[i];
    #pragma unroll
    for (int o = 16; o; o >>= 1) s += __shfl_xor_sync(0xffffffffu, s, o);
    if (lane == 0) logits[warp] = s;
    __syncthreads();
    if (threadIdx.x == 0) {
        int i0 = 0; float v0 = logits[0];
        #pragma unroll
        for (int e = 1; e < NE; e++) if (logits[e] > v0) { v0 = logits[e]; i0 = e; }
        int i1 = -1; float v1 = -1e30f;
        #pragma unroll
        for (int e = 0; e < NE; e++)
            if (e != i0 && logits[e] > v1) { v1 = logits[e]; i1 = e; }
        float ex = __expf(v1 - v0);
        float w0 = 1.f / (1.f + ex);
        float w1 = ex  / (1.f + ex);
        int s0 = atomicAdd(&g_cnt[i0], 1);
        g_pid[i0 * NPAIR + s0] = t * 2;     g_wt[i0 * NPAIR + s0] = w0;
        int s1 = atomicAdd(&g_cnt[i1], 1);
        g_pid[i1 * NPAIR + s1] = t * 2 + 1; g_wt[i1 * NPAIR + s1] = w1;
    }
}

// ---------------- merged hi/lo split: x/wg/wu -> bf16, wd -> fp16 ------------
#define NX4 (T_TOKENS * D_MODEL / 4)
#define NW4 (NE * D_FFN * D_MODEL / 4)
__global__ __launch_bounds__(256) void split_all_kernel(const float4* __restrict__ x,
                                                        const float4* __restrict__ wg,
                                                        const float4* __restrict__ wu,
                                                        const float4* __restrict__ wd) {
    const int totalp = (NX4 + 3 * NW4) / 2;
    union U8b { __nv_bfloat16 b[8]; uint4 u; };
    union U8h { __half h[8]; uint4 u; };
    for (int p = blockIdx.x * blockDim.x + threadIdx.x; p < totalp;
         p += gridDim.x * blockDim.x) {
        int li = p * 2;
        const float4* src;
        uint4 *h4, *l4;
        bool is_fp16 = false;
        if (li < NX4)                { src = x;  h4 = (uint4*)g_xhi;  l4 = (uint4*)g_xlo;  }
        else if ((li -= NX4) < NW4)  { src = wg; h4 = (uint4*)g_wghi; l4 = (uint4*)g_wglo; }
        else if ((li -= NW4) < NW4)  { src = wu; h4 = (uint4*)g_wuhi; l4 = (uint4*)g_wulo; }
        else { li -= NW4; src = wd; h4 = (uint4*)g_wdhi; l4 = (uint4*)g_wdlo; is_fp16 = true; }
        float4 v0 = src[li], v1 = src[li + 1];
        float vv[8] = { v0.x, v0.y, v0.z, v0.w, v1.x, v1.y, v1.z, v1.w };
        if (is_fp16) {
            U8h H, L;
            #pragma unroll
            for (int k = 0; k < 8; ++k) {
                H.h[k] = __float2half_rn(vv[k]);
                L.h[k] = __float2half_rn(vv[k] - __half2float(H.h[k]));
            }
            h4[li >> 1] = H.u;
            l4[li >> 1] = L.u;
        } else {
            U8b H, L;
            #pragma unroll
            for (int k = 0; k < 8; ++k) {
                H.b[k] = __float2bfloat16(vv[k]);
                L.b[k] = __float2bfloat16(vv[k] - __bfloat162float(H.b[k]));
            }
            h4[li >> 1] = H.u;
            l4[li >> 1] = L.u;
        }
    }
}

// =============================================================================
// FUSED persistent MoE kernel. Gateup tiles: bf16 3-term (R15 body, H->fp16).
// Down tiles: fp16 2-term (H16 single x Wd hi/lo), 24KB stages, packed rows.
// =============================================================================
#define GU_STAGE 32768
#define DN_STAGE 24576
#define FU_SMEM (2048 + 3 * GU_STAGE)
__global__ __launch_bounds__(256, 2) void moe_fused_kernel() {
    extern __shared__ __align__(1024) char smem[];
    const uint32_t sb = smem_u32(smem);
    int*   s_pid  = (int*)smem;
    float* s_w    = (float*)(smem + 512);
    int*   s_offg = (int*)(smem + 1024);
    int*   s_offd = (int*)(smem + 1060);
    int*   s_idx  = (int*)(smem + 1100);
    const int tid  = threadIdx.x;
    const int wid  = tid >> 5, lane = tid & 31;

    if (tid == 0) {
        int ag = 0, ad = 0;
        s_offg[0] = 0; s_offd[0] = 0;
        #pragma unroll
        for (int e2 = 0; e2 < NE; ++e2) {
            const int mbc = (g_cnt[e2] + 127) >> 7;
            ag += mbc * (D_FFN / 64);
            ad += mbc * (D_MODEL / 128);
            s_offg[e2 + 1] = ag;
            s_offd[e2 + 1] = ad;
        }
    }
    const uint32_t klane = (uint32_t)((lane >> 4) * 16);
    __syncthreads();
    const int totalg = s_offg[NE];
    const int totald = s_offd[NE];

    while (true) {
        __syncthreads();
        if (tid == 0) *s_idx = atomicAdd(&g_ctr, 1);
        __syncthreads();
        const int idx = *s_idx;
        if (idx >= totalg + totald) break;

        if (idx < totalg) {
            // ================= GATEUP TILE (bf16 3-term) =================
            const int wm = wid >> 1, wn = wid & 1;
            int e = 0;
            while (idx >= s_offg[e + 1]) ++e;
            const int local = idx - s_offg[e];
            const int mb = local >> 5, nb = local & 31;
            const int ne = g_cnt[e];
            const int m0 = mb * 128, n0 = nb * 64;

            if (tid < 128) {
                int r = m0 + tid;
                s_pid[tid] = g_pid[e * NPAIR + (r < ne ? r : m0)];
            }
            __syncthreads();

            const int rowA = tid >> 1, sa = (tid & 1) * 2;
            uint32_t dAh[2], dAl[2];
            #pragma unroll
            for (int j = 0; j < 2; ++j) {
                dAh[j] = swz((uint32_t)(rowA * 128 + (sa + j) * 16));
                dAl[j] = swz((uint32_t)(rowA * 128 + 64 + (sa + j) * 16));
            }
            const int rowB = tid >> 2, sgB = tid & 3;
            const uint32_t dBgh = swz((uint32_t)(16384 + rowB * 128 + sgB * 16));
            const uint32_t dBgl = swz((uint32_t)(16384 + rowB * 128 + 64 + sgB * 16));
            const uint32_t dBuh = swz((uint32_t)(24576 + rowB * 128 + sgB * 16));
            const uint32_t dBul = swz((uint32_t)(24576 + rowB * 128 + 64 + sgB * 16));
            uint32_t aofs[2], bofs[2];
            #pragma unroll
            for (int i = 0; i < 2; ++i)
                aofs[i] = swz((uint32_t)((wm * 32 + i * 16 + (lane & 15)) * 128 + klane));
            #pragma unroll
            for (int j = 0; j < 2; ++j)
                bofs[j] = swz((uint32_t)(16384 + (wn * 32 + j * 16 + (lane & 15)) * 128 + klane));

            const __nv_bfloat16* gxh = g_xhi + (size_t)(s_pid[rowA] >> 1) * D_MODEL + sa * 8;
            const __nv_bfloat16* gxl = g_xlo + (size_t)(s_pid[rowA] >> 1) * D_MODEL + sa * 8;
            const size_t boff = ((size_t)e * D_FFN + n0 + rowB) * D_MODEL + sgB * 8;
            const __nv_bfloat16* gbgh = g_wghi + boff;
            const __nv_bfloat16* gbgl = g_wglo + boff;
            const __nv_bfloat16* gbuh = g_wuhi + boff;
            const __nv_bfloat16* gbul = g_wulo + boff;

#define GU_LOAD(kb, st) do {                                                    \
        const uint32_t db = sb + 2048 + (st) * GU_STAGE;                        \
        _Pragma("unroll") for (int j = 0; j < 2; ++j) {                         \
            CP_ASYNC(db + dAh[j], gxh + (kb) + j * 8);                          \
            CP_ASYNC(db + dAl[j], gxl + (kb) + j * 8);                          \
        }                                                                       \
        CP_ASYNC(db + dBgh, gbgh + (kb));                                       \
        CP_ASYNC(db + dBgl, gbgl + (kb));                                       \
        CP_ASYNC(db + dBuh, gbuh + (kb));                                       \
        CP_ASYNC(db + dBul, gbul + (kb)); } while (0)

            float ag[2][4][4], au[2][4][4];
            #pragma unroll
            for (int i = 0; i < 2; ++i)
                #pragma unroll
                for (int j = 0; j < 4; ++j)
                    #pragma unroll
                    for (int q = 0; q < 4; ++q) { ag[i][j][q] = 0.f; au[i][j][q] = 0.f; }

            const int NC = D_MODEL / 32;
            GU_LOAD(0, 0);  CP_COMMIT();
            GU_LOAD(32, 1); CP_COMMIT();
            for (int ch = 0; ch < NC; ++ch) {
                if (ch == NC - 1) CP_WAIT(0); else CP_WAIT(1);
                __syncthreads();
                if (ch + 2 < NC) { GU_LOAD((ch + 2) * 32, (ch + 2) % 3); CP_COMMIT(); }
                const uint32_t base = sb + 2048 + (ch % 3) * GU_STAGE;
                #pragma unroll
                for (int s = 0; s < 2; ++s) {
                    const uint32_t sd = (uint32_t)(s * 32);
                    uint32_t ah[2][4], al[2][4];
                    #pragma unroll
                    for (int i = 0; i < 2; ++i) {
                        ldsm4(ah[i], base + (aofs[i] ^ sd));
                        ldsm4(al[i], base + (aofs[i] ^ (sd | 64u)));
                    }
                    {   // gate hi
                        uint32_t b[2][4];
                        ldsm4(b[0], base + (bofs[0] ^ sd));
                        ldsm4(b[1], base + (bofs[1] ^ sd));
                        #pragma unroll
                        for (int i = 0; i < 2; ++i)
                            #pragma unroll
                            for (int j = 0; j < 2; ++j)
                                #pragma unroll
                                for (int h = 0; h < 2; ++h)
                                    mma16816(ag[i][j * 2 + h], ah[i], b[j][h], b[j][h + 2]);
                        #pragma unroll
                        for (int i = 0; i < 2; ++i)
                            #pragma unroll
                            for (int j = 0; j < 2; ++j)
                                #pragma unroll
                                for (int h = 0; h < 2; ++h)
                                    mma16816(ag[i][j * 2 + h], al[i], b[j][h], b[j][h + 2]);
                    }
                    {   // gate lo
                        uint32_t b[2][4];
                        ldsm4(b[0], base + (bofs[0] ^ (sd | 64u)));
                        ldsm4(b[1], base + (bofs[1] ^ (sd | 64u)));
                        #pragma unroll
                        for (int i = 0; i < 2; ++i)
                            #pragma unroll
                            for (int j = 0; j < 2; ++j)
                                #pragma unroll
                                for (int h = 0; h < 2; ++h)
                                    mma16816(ag[i][j * 2 + h], ah[i], b[j][h], b[j][h + 2]);
                    }
                    {   // up hi
                        uint32_t b[2][4];
                        ldsm4(b[0], base + (bofs[0] ^ (sd | 8192u)));
                        ldsm4(b[1], base + (bofs[1] ^ (sd | 8192u)));
                        #pragma unroll
                        for (int i = 0; i < 2; ++i)
                            #pragma unroll
                            for (int j = 0; j < 2; ++j)
                                #pragma unroll
                                for (int h = 0; h < 2; ++h)
                                    mma16816(au[i][j * 2 + h], ah[i], b[j][h], b[j][h + 2]);
                        #pragma unroll
                        for (int i = 0; i < 2; ++i)
                            #pragma unroll
                            for (int j = 0; j < 2; ++j)
                                #pragma unroll
                                for (int h = 0; h < 2; ++h)
                                    mma16816(au[i][j * 2 + h], al[i], b[j][h], b[j][h + 2]);
                    }
                    {   // up lo
                        uint32_t b[2][4];
                        ldsm4(b[0], base + (bofs[0] ^ (sd | 8256u)));
                        ldsm4(b[1], base + (bofs[1] ^ (sd | 8256u)));
                        #pragma unroll
                        for (int i = 0; i < 2; ++i)
                            #pragma unroll
                            for (int j = 0; j < 2; ++j)
                                #pragma unroll
                                for (int h = 0; h < 2; ++h)
                                    mma16816(au[i][j * 2 + h], ah[i], b[j][h], b[j][h + 2]);
                    }
                }
            }
#undef GU_LOAD

            // epilogue: SwiGLU -> H (single fp16)
            #pragma unroll
            for (int i = 0; i < 2; ++i) {
                const int m1 = wm * 32 + i * 16 + (lane >> 2);
                const int m2 = m1 + 8;
                const int pid1 = s_pid[m1], pid2 = s_pid[m2];
                #pragma unroll
                for (int jn = 0; jn < 4; ++jn) {
                    const int col = n0 + wn * 32 + jn * 8 + (lane & 3) * 2;
                    const float* cg = ag[i][jn];
                    const float* cu = au[i][jn];
                    float h0 = (cg[0] / (1.f + __expf(-cg[0]))) * cu[0];
                    float h1 = (cg[1] / (1.f + __expf(-cg[1]))) * cu[1];
                    float h2 = (cg[2] / (1.f + __expf(-cg[2]))) * cu[2];
                    float h3 = (cg[3] / (1.f + __expf(-cg[3]))) * cu[3];
                    *(half2*)&g_H16[(size_t)pid1 * D_FFN + col] = __floats2half2_rn(h0, h1);
                    *(half2*)&g_H16[(size_t)pid2 * D_FFN + col] = __floats2half2_rn(h2, h3);
                }
            }
            __threadfence();
            __syncthreads();
            if (tid == 0) atomicAdd(&g_ready[e * 64 + mb], 1);
        } else {
            // ================= DOWN TILE (fp16 2-term) =================
            const int didx = idx - totalg;
            const int wm = wid >> 2, wn = wid & 3;
            int e = 0;
            while (didx >= s_offd[e + 1]) ++e;
            const int local = didx - s_offd[e];
            const int mb = local >> 3, nb = local & 7;
            const int ne = g_cnt[e];
            const int m0 = mb * 128, n0 = nb * 128;

            if (tid == 0) {
                const int* rp = &g_ready[e * 64 + mb];
                int v;
                do {
                    asm volatile("ld.global.acquire.gpu.b32 %0, [%1];" : "=r"(v) : "l"(rp));
                } while (v < 32);
            }
            __syncthreads();

            if (tid < 128) {
                int r  = m0 + tid;
                int rr = (r < ne) ? r : m0;
                s_pid[tid] = g_pid[e * NPAIR + rr];
                s_w[tid]   = g_wt [e * NPAIR + rr];
            }
            __syncthreads();

            // packed rows: data-row r occupies 64B at (r>>1)*128 + (r&1)*64.
            // Regions: A @0 (8K), Bh @8192 (8K), Bl @16384 (8K). Stage 24KB.
            const int rA  = tid >> 1;
            const int sg0 = (tid & 1) * 2;
            uint32_t dA[2];
            #pragma unroll
            for (int j = 0; j < 2; ++j)
                dA[j] = swz((uint32_t)((rA >> 1) * 128 + (rA & 1) * 64 + (sg0 + j) * 16));
            const __half* gah = g_H16 + (size_t)s_pid[rA] * D_FFN + sg0 * 8;
            const size_t boff = ((size_t)e * D_MODEL + n0 + rA) * D_FFN + sg0 * 8;
            const __half* gbh = g_wdhi + boff;
            const __half* gbl = g_wdlo + boff;

            uint32_t aofs[4], bofs[2];
            #pragma unroll
            for (int i = 0; i < 4; ++i) {
                const int R = wm * 64 + i * 16 + (lane & 15);
                aofs[i] = swz((uint32_t)((R >> 1) * 128 + (R & 1) * 64) + klane);
            }
            #pragma unroll
            for (int j = 0; j < 2; ++j) {
                const int R = wn * 32 + j * 16 + (lane & 15);
                bofs[j] = swz((uint32_t)(8192 + (R >> 1) * 128 + (R & 1) * 64) + klane);
            }

#define DN_LOAD(kb, st) do {                                                    \
        const uint32_t db = sb + 2048 + (st) * DN_STAGE;                        \
        _Pragma("unroll") for (int j = 0; j < 2; ++j) {                         \
            CP_ASYNC(db + dA[j],          gah + (kb) + j * 8);                  \
            CP_ASYNC(db + dA[j] + 8192,   gbh + (kb) + j * 8);                  \
            CP_ASYNC(db + dA[j] + 16384,  gbl + (kb) + j * 8);                  \
        } } while (0)

            float acc[4][4][4];
            #pragma unroll
            for (int i = 0; i < 4; ++i)
                #pragma unroll
                for (int j = 0; j < 4; ++j)
                    #pragma unroll
                    for (int q = 0; q < 4; ++q) acc[i][j][q] = 0.f;

            const int NC = D_FFN / 32;   // 64 chunks of 32 fp16 elements
            DN_LOAD(0, 0);  CP_COMMIT();
            DN_LOAD(32, 1); CP_COMMIT();
            for (int ch = 0; ch < NC; ++ch) {
                if (ch == NC - 1) CP_WAIT(0); else CP_WAIT(1);
                __syncthreads();
                if (ch + 2 < NC) { DN_LOAD((ch + 2) * 32, (ch + 2) % 3); CP_COMMIT(); }
                const uint32_t base = sb + 2048 + (ch % 3) * DN_STAGE;
                #pragma unroll
                for (int s = 0; s < 2; ++s) {
                    const uint32_t sd = (uint32_t)(s * 32);
                    uint32_t ah[4][4];
                    #pragma unroll
                    for (int i = 0; i < 4; ++i)
                        ldsm4(ah[i], base + (aofs[i] ^ sd));
                    uint32_t bh[2][4], bl[2][4];
                    ldsm4(bh[0], base + (bofs[0] ^ sd));
                    ldsm4(bh[1], base + (bofs[1] ^ sd));
                    ldsm4(bl[0], base + (bofs[0] ^ sd ^ 24576u));
                    ldsm4(bl[1], base + (bofs[1] ^ sd ^ 24576u));
                    // pass 1: ah x bh
                    #pragma unroll
                    for (int i = 0; i < 4; ++i)
                        #pragma unroll
                        for (int j = 0; j < 2; ++j)
                            #pragma unroll
                            for (int h = 0; h < 2; ++h)
                                mma16816h(acc[i][j * 2 + h], ah[i], bh[j][h], bh[j][h + 2]);
                    // pass 2: ah x bl
                    #pragma unroll
                    for (int i = 0; i < 4; ++i)
                        #pragma unroll
                        for (int j = 0; j < 2; ++j)
                            #pragma unroll
                            for (int h = 0; h < 2; ++h)
                                mma16816h(acc[i][j * 2 + h], ah[i], bl[j][h], bl[j][h + 2]);
                }
            }
#undef DN_LOAD

            #pragma unroll
            for (int i = 0; i < 4; ++i) {
                const int m1 = wm * 64 + i * 16 + (lane >> 2);
                const int m2 = m1 + 8;
                const int pid1 = s_pid[m1], pid2 = s_pid[m2];
                const float w1 = s_w[m1], w2 = s_w[m2];
                #pragma unroll
                for (int jn = 0; jn < 4; ++jn) {
                    const int col = n0 + wn * 32 + jn * 8 + (lane & 3) * 2;
                    const float* c = acc[i][jn];
                    float2 v1 = { c[0] * w1, c[1] * w1 };
                    float2 v2 = { c[2] * w2, c[3] * w2 };
                    *(float2*)&g_Y[(size_t)pid1 * D_MODEL + col] = v1;
                    *(float2*)&g_Y[(size_t)pid2 * D_MODEL + col] = v2;
                }
            }
        }
    }
}

// ---------------- kernel: combine pairs + LayerNorm --------------------------
__global__ __launch_bounds__(256) void combine_ln_kernel(const float* __restrict__ gamma,
                                                         const float* __restrict__ beta,
                                                         float* __restrict__ out) {
    const int t   = blockIdx.x;
    const int tid = threadIdx.x;
    const float4 a = ((const float4*)(g_Y + (size_t)(2 * t)     * D_MODEL))[tid];
    const float4 b = ((const float4*)(g_Y + (size_t)(2 * t + 1) * D_MODEL))[tid];
    float4 v = { a.x + b.x, a.y + b.y, a.z + b.z, a.w + b.w };

    float s  = v.x + v.y + v.z + v.w;
    float sq = v.x * v.x + v.y * v.y + v.z * v.z + v.w * v.w;
    #pragma unroll
    for (int o = 16; o; o >>= 1) {
        s  += __shfl_xor_sync(0xffffffffu, s,  o);
        sq += __shfl_xor_sync(0xffffffffu, sq, o);
    }
    __shared__ float rs_[8], rq_[8];
    __shared__ float s_mu, s_rs;
    if ((tid & 31) == 0) { rs_[tid >> 5] = s; rq_[tid >> 5] = sq; }
    __syncthreads();
    if (tid == 0) {
        float S = 0.f, Q = 0.f;
        #pragma unroll
        for (int i = 0; i < 8; i++) { S += rs_[i]; Q += rq_[i]; }
        float mu  = S / (float)D_MODEL;
        float var = Q / (float)D_MODEL - mu * mu;
        s_mu = mu;
        s_rs = rsqrtf(var + 1e-5f);
    }
    __syncthreads();
    const float mu = s_mu, rs = s_rs;
    const float4 gg = ((const float4*)gamma)[tid];
    const float4 bb = ((const float4*)beta)[tid];
    float4 o;
    o.x = (v.x - mu) * rs * gg.x + bb.x;
    o.y = (v.y - mu) * rs * gg.y + bb.y;
    o.z = (v.z - mu) * rs * gg.z + bb.z;
    o.w = (v.w - mu) * rs * gg.w + bb.w;
    ((float4*)out)[(size_t)t * (D_MODEL / 4) + tid] = o;
}

// ---------------- launch ------------------------------------------------------
extern "C" void kernel_launch(void* const* d_in, const int* in_sizes, int n_in,
                              void* d_out, int out_size) {
    const float* x     = (const float*)d_in[0];
    const float* wr    = (const float*)d_in[1];
    const float* wg    = (const float*)d_in[2];
    const float* wu    = (const float*)d_in[3];
    const float* wd    = (const float*)d_in[4];
    const float* gamma = (const float*)d_in[5];
    const float* beta  = (const float*)d_in[6];
    float* out = (float*)d_out;

    cudaFuncSetAttribute(moe_fused_kernel, cudaFuncAttributeMaxDynamicSharedMemorySize, FU_SMEM);

    zero_cnt_kernel<<<1, 512>>>();
    router_kernel<<<T_TOKENS, 256>>>(x, wr);
    split_all_kernel<<<6656, 256>>>((const float4*)x, (const float4*)wg,
                                    (const float4*)wu, (const float4*)wd);
    moe_fused_kernel<<<304, 256, FU_SMEM>>>();
    combine_ln_kernel<<<T_TOKENS, 256>>>(gamma, beta, out);
}

// round 17
// speedup vs baseline: 1.5543x; 1.2554x over previous
#include <cuda_runtime.h>
#include <cuda_bf16.h>
#include <cuda_fp16.h>
#include <math.h>
#include <stdint.h>

#define D_MODEL 1024
#define D_FFN   2048
#define NE      8
#define T_TOKENS 4096
#define NPAIR   8192

// ---------------- scratch (device globals) ----------------------------------
__device__ int   g_cnt[NE];
__device__ int   g_ctr;
__device__ int   g_ready[NE * 64];
__device__ int   g_pid[NE * NPAIR];
__device__ float g_wt [NE * NPAIR];
__device__ __half g_x16 [(size_t)T_TOKENS * D_MODEL];
__device__ __half g_wghi[(size_t)NE * D_FFN * D_MODEL];
__device__ __half g_wglo[(size_t)NE * D_FFN * D_MODEL];
__device__ __half g_wuhi[(size_t)NE * D_FFN * D_MODEL];
__device__ __half g_wulo[(size_t)NE * D_FFN * D_MODEL];
__device__ __half g_wdhi[(size_t)NE * D_MODEL * D_FFN];
__device__ __half g_wdlo[(size_t)NE * D_MODEL * D_FFN];
__device__ __half g_H16 [(size_t)NPAIR * D_FFN];
__device__ float g_Y[(size_t)NPAIR * D_MODEL];

// ---------------- portable PTX helpers ---------------------------------------
__device__ __forceinline__ uint32_t smem_u32(const void* p) {
    uint32_t a;
    asm("{ .reg .u64 t; cvta.to.shared.u64 t, %1; cvt.u32.u64 %0, t; }" : "=r"(a) : "l"(p));
    return a;
}
#define CP_ASYNC(dst, src) \
    asm volatile("cp.async.cg.shared.global [%0], [%1], 16;" :: "r"(dst), "l"(src))
#define CP_COMMIT() asm volatile("cp.async.commit_group;" ::: "memory")
#define CP_WAIT(n)  asm volatile("cp.async.wait_group %0;" :: "n"(n) : "memory")

__device__ __forceinline__ uint32_t swz(uint32_t o) { return o ^ ((o >> 3) & 0x70); }

__device__ __forceinline__ void ldsm4(uint32_t r[4], uint32_t addr) {
    asm volatile("ldmatrix.sync.aligned.m8n8.x4.shared.b16 {%0,%1,%2,%3}, [%4];"
                 : "=r"(r[0]), "=r"(r[1]), "=r"(r[2]), "=r"(r[3]) : "r"(addr));
}
__device__ __forceinline__ void mma16816h(float* c, const uint32_t a[4],
                                          uint32_t b0, uint32_t b1) {
    asm volatile(
        "mma.sync.aligned.m16n8k16.row.col.f32.f16.f16.f32 "
        "{%0,%1,%2,%3}, {%4,%5,%6,%7}, {%8,%9}, {%0,%1,%2,%3};"
        : "+f"(c[0]), "+f"(c[1]), "+f"(c[2]), "+f"(c[3])
        : "r"(a[0]), "r"(a[1]), "r"(a[2]), "r"(a[3]), "r"(b0), "r"(b1));
}

// ---------------- kernel 0: reset counters ----------------------------------
__global__ __launch_bounds__(512) void zero_cnt_kernel() {
    const int t = threadIdx.x;
    if (t < NE) g_cnt[t] = 0;
    if (t == NE) g_ctr = 0;
    if (t < NE * 64) g_ready[t] = 0;
}

// ---------------- kernel 1: router ------------------------------------------
__global__ __launch_bounds__(256) void router_kernel(const float* __restrict__ x,
                                                     const float* __restrict__ wr) {
    const int t = blockIdx.x;
    const int warp = threadIdx.x >> 5, lane = threadIdx.x & 31;
    __shared__ float logits[NE];
    const float* xr = x + (size_t)t * D_MODEL;
    const float* w  = wr + (size_t)warp * D_MODEL;
    float s = 0.f;
    #pragma unroll 8
    for (int i = lane; i < D_MODEL; i += 32) s += xr[i] * w[i];
    #pragma unroll
    for (int o = 16; o; o >>= 1) s += __shfl_xor_sync(0xffffffffu, s, o);
    if (lane == 0) logits[warp] = s;
    __syncthreads();
    if (threadIdx.x == 0) {
        int i0 = 0; float v0 = logits[0];
        #pragma unroll
        for (int e = 1; e < NE; e++) if (logits[e] > v0) { v0 = logits[e]; i0 = e; }
        int i1 = -1; float v1 = -1e30f;
        #pragma unroll
        for (int e = 0; e < NE; e++)
            if (e != i0 && logits[e] > v1) { v1 = logits[e]; i1 = e; }
        float ex = __expf(v1 - v0);
        float w0 = 1.f / (1.f + ex);
        float w1 = ex  / (1.f + ex);
        int s0 = atomicAdd(&g_cnt[i0], 1);
        g_pid[i0 * NPAIR + s0] = t * 2;     g_wt[i0 * NPAIR + s0] = w0;
        int s1 = atomicAdd(&g_cnt[i1], 1);
        g_pid[i1 * NPAIR + s1] = t * 2 + 1; g_wt[i1 * NPAIR + s1] = w1;
    }
}

// ---------------- merged split: x -> fp16 single; wg/wu/wd -> fp16 hi/lo ----
#define NX4 (T_TOKENS * D_MODEL / 4)
#define NW4 (NE * D_FFN * D_MODEL / 4)
__global__ __launch_bounds__(256) void split_all_kernel(const float4* __restrict__ x,
                                                        const float4* __restrict__ wg,
                                                        const float4* __restrict__ wu,
                                                        const float4* __restrict__ wd) {
    const int totalp = (NX4 + 3 * NW4) / 2;
    union U8h { __half h[8]; uint4 u; };
    for (int p = blockIdx.x * blockDim.x + threadIdx.x; p < totalp;
         p += gridDim.x * blockDim.x) {
        int li = p * 2;
        if (li < NX4) {
            float4 v0 = x[li], v1 = x[li + 1];
            float vv[8] = { v0.x, v0.y, v0.z, v0.w, v1.x, v1.y, v1.z, v1.w };
            U8h H;
            #pragma unroll
            for (int k = 0; k < 8; ++k) H.h[k] = __float2half_rn(vv[k]);
            ((uint4*)g_x16)[li >> 1] = H.u;
            continue;
        }
        li -= NX4;
        const float4* src;
        uint4 *h4, *l4;
        if (li < NW4)                { src = wg; h4 = (uint4*)g_wghi; l4 = (uint4*)g_wglo; }
        else if ((li -= NW4) < NW4)  { src = wu; h4 = (uint4*)g_wuhi; l4 = (uint4*)g_wulo; }
        else { li -= NW4; src = wd; h4 = (uint4*)g_wdhi; l4 = (uint4*)g_wdlo; }
        float4 v0 = src[li], v1 = src[li + 1];
        float vv[8] = { v0.x, v0.y, v0.z, v0.w, v1.x, v1.y, v1.z, v1.w };
        U8h H, L;
        #pragma unroll
        for (int k = 0; k < 8; ++k) {
            H.h[k] = __float2half_rn(vv[k]);
            L.h[k] = __float2half_rn(vv[k] - __half2float(H.h[k]));
        }
        h4[li >> 1] = H.u;
        l4[li >> 1] = L.u;
    }
}

// =============================================================================
// FUSED persistent MoE kernel, all-fp16 operands, packed 64B rows everywhere.
// Gateup: x16 single x {Wg,Wu} hi/lo (4 MMA units). Down: H16 x Wd hi/lo (2).
// Stage 24KB both phases. Packed row r: byte (r>>1)*128 + (r&1)*64.
// =============================================================================
#define ST_STAGE 24576
#define FU_SMEM (2048 + 3 * ST_STAGE)
__global__ __launch_bounds__(256, 2) void moe_fused_kernel() {
    extern __shared__ __align__(1024) char smem[];
    const uint32_t sb = smem_u32(smem);
    int*   s_pid  = (int*)smem;
    float* s_w    = (float*)(smem + 512);
    int*   s_offg = (int*)(smem + 1024);
    int*   s_offd = (int*)(smem + 1060);
    int*   s_idx  = (int*)(smem + 1100);
    const int tid  = threadIdx.x;
    const int wid  = tid >> 5, lane = tid & 31;

    if (tid == 0) {
        int ag = 0, ad = 0;
        s_offg[0] = 0; s_offd[0] = 0;
        #pragma unroll
        for (int e2 = 0; e2 < NE; ++e2) {
            const int mbc = (g_cnt[e2] + 127) >> 7;
            ag += mbc * (D_FFN / 64);
            ad += mbc * (D_MODEL / 128);
            s_offg[e2 + 1] = ag;
            s_offd[e2 + 1] = ad;
        }
    }
    const uint32_t klane = (uint32_t)((lane >> 4) * 16);
    // shared A cp.async geometry (both phases): 128 packed rows, 2 segs/thread
    const int rA  = tid >> 1;
    const int sg0 = (tid & 1) * 2;
    uint32_t dA[2];
    #pragma unroll
    for (int j = 0; j < 2; ++j)
        dA[j] = swz((uint32_t)((rA >> 1) * 128 + (rA & 1) * 64 + (sg0 + j) * 16));
    __syncthreads();
    const int totalg = s_offg[NE];
    const int totald = s_offd[NE];

    while (true) {
        __syncthreads();
        if (tid == 0) *s_idx = atomicAdd(&g_ctr, 1);
        __syncthreads();
        const int idx = *s_idx;
        if (idx >= totalg + totald) break;

        if (idx < totalg) {
            // ============ GATEUP TILE (fp16: x single x W hi/lo) ============
            const int wm = wid >> 1, wn = wid & 1;
            int e = 0;
            while (idx >= s_offg[e + 1]) ++e;
            const int local = idx - s_offg[e];
            const int mb = local >> 5, nb = local & 31;
            const int ne = g_cnt[e];
            const int m0 = mb * 128, n0 = nb * 64;

            if (tid < 128) {
                int r = m0 + tid;
                s_pid[tid] = g_pid[e * NPAIR + (r < ne ? r : m0)];
            }
            __syncthreads();

            // B cp.async: 64 packed rows per region, 4 regions, 1 seg/thread each
            const int rowB = tid >> 2, sgB = tid & 3;
            const uint32_t dB = swz((uint32_t)(8192 + (rowB >> 1) * 128
                                               + (rowB & 1) * 64 + sgB * 16));
            const __half* gax = g_x16 + (size_t)(s_pid[rA] >> 1) * D_MODEL + sg0 * 8;
            const size_t boff = ((size_t)e * D_FFN + n0 + rowB) * D_MODEL + sgB * 8;
            const __half* gbgh = g_wghi + boff;
            const __half* gbgl = g_wglo + boff;
            const __half* gbuh = g_wuhi + boff;
            const __half* gbul = g_wulo + boff;

            uint32_t aofs[2], bofs[2];
            #pragma unroll
            for (int i = 0; i < 2; ++i) {
                const int R = wm * 32 + i * 16 + (lane & 15);
                aofs[i] = swz((uint32_t)((R >> 1) * 128 + (R & 1) * 64) + klane);
            }
            #pragma unroll
            for (int j = 0; j < 2; ++j) {
                const int R = wn * 32 + j * 16 + (lane & 15);
                bofs[j] = swz((uint32_t)(8192 + (R >> 1) * 128 + (R & 1) * 64) + klane);
            }

#define GU_LOAD(kb, st) do {                                                    \
        const uint32_t db = sb + 2048 + (st) * ST_STAGE;                        \
        _Pragma("unroll") for (int j = 0; j < 2; ++j)                           \
            CP_ASYNC(db + dA[j], gax + (kb) + j * 8);                           \
        CP_ASYNC(db + dB,          gbgh + (kb));                                \
        CP_ASYNC(db + (dB ^ 4096u),  gbgl + (kb));                              \
        CP_ASYNC(db + (dB ^ 24576u), gbuh + (kb));                              \
        CP_ASYNC(db + (dB ^ 28672u), gbul + (kb)); } while (0)

            float ag[2][4][4], au[2][4][4];
            #pragma unroll
            for (int i = 0; i < 2; ++i)
                #pragma unroll
                for (int j = 0; j < 4; ++j)
                    #pragma unroll
                    for (int q = 0; q < 4; ++q) { ag[i][j][q] = 0.f; au[i][j][q] = 0.f; }

            const int NC = D_MODEL / 32;
            GU_LOAD(0, 0);  CP_COMMIT();
            GU_LOAD(32, 1); CP_COMMIT();
            for (int ch = 0; ch < NC; ++ch) {
                if (ch == NC - 1) CP_WAIT(0); else CP_WAIT(1);
                __syncthreads();
                if (ch + 2 < NC) { GU_LOAD((ch + 2) * 32, (ch + 2) % 3); CP_COMMIT(); }
                const uint32_t base = sb + 2048 + (ch % 3) * ST_STAGE;
                #pragma unroll
                for (int s = 0; s < 2; ++s) {
                    const uint32_t sd = (uint32_t)(s * 32);
                    uint32_t ah[2][4];
                    #pragma unroll
                    for (int i = 0; i < 2; ++i)
                        ldsm4(ah[i], base + (aofs[i] ^ sd));
                    uint32_t b[2][4];
                    // gate hi
                    ldsm4(b[0], base + (bofs[0] ^ sd));
                    ldsm4(b[1], base + (bofs[1] ^ sd));
                    #pragma unroll
                    for (int i = 0; i < 2; ++i)
                        #pragma unroll
                        for (int j = 0; j < 2; ++j)
                            #pragma unroll
                            for (int h = 0; h < 2; ++h)
                                mma16816h(ag[i][j * 2 + h], ah[i], b[j][h], b[j][h + 2]);
                    // gate lo
                    ldsm4(b[0], base + (bofs[0] ^ sd ^ 4096u));
                    ldsm4(b[1], base + (bofs[1] ^ sd ^ 4096u));
                    #pragma unroll
                    for (int i = 0; i < 2; ++i)
                        #pragma unroll
                        for (int j = 0; j < 2; ++j)
                            #pragma unroll
                            for (int h = 0; h < 2; ++h)
                                mma16816h(ag[i][j * 2 + h], ah[i], b[j][h], b[j][h + 2]);
                    // up hi
                    ldsm4(b[0], base + (bofs[0] ^ sd ^ 24576u));
                    ldsm4(b[1], base + (bofs[1] ^ sd ^ 24576u));
                    #pragma unroll
                    for (int i = 0; i < 2; ++i)
                        #pragma unroll
                        for (int j = 0; j < 2; ++j)
                            #pragma unroll
                            for (int h = 0; h < 2; ++h)
                                mma16816h(au[i][j * 2 + h], ah[i], b[j][h], b[j][h + 2]);
                    // up lo
                    ldsm4(b[0], base + (bofs[0] ^ sd ^ 28672u));
                    ldsm4(b[1], base + (bofs[1] ^ sd ^ 28672u));
                    #pragma unroll
                    for (int i = 0; i < 2; ++i)
                        #pragma unroll
                        for (int j = 0; j < 2; ++j)
                            #pragma unroll
                            for (int h = 0; h < 2; ++h)
                                mma16816h(au[i][j * 2 + h], ah[i], b[j][h], b[j][h + 2]);
                }
            }
#undef GU_LOAD

            // epilogue: SwiGLU -> H (single fp16)
            #pragma unroll
            for (int i = 0; i < 2; ++i) {
                const int m1 = wm * 32 + i * 16 + (lane >> 2);
                const int m2 = m1 + 8;
                const int pid1 = s_pid[m1], pid2 = s_pid[m2];
                #pragma unroll
                for (int jn = 0; jn < 4; ++jn) {
                    const int col = n0 + wn * 32 + jn * 8 + (lane & 3) * 2;
                    const float* cg = ag[i][jn];
                    const float* cu = au[i][jn];
                    float h0 = (cg[0] / (1.f + __expf(-cg[0]))) * cu[0];
                    float h1 = (cg[1] / (1.f + __expf(-cg[1]))) * cu[1];
                    float h2 = (cg[2] / (1.f + __expf(-cg[2]))) * cu[2];
                    float h3 = (cg[3] / (1.f + __expf(-cg[3]))) * cu[3];
                    *(half2*)&g_H16[(size_t)pid1 * D_FFN + col] = __floats2half2_rn(h0, h1);
                    *(half2*)&g_H16[(size_t)pid2 * D_FFN + col] = __floats2half2_rn(h2, h3);
                }
            }
            __threadfence();
            __syncthreads();
            if (tid == 0) atomicAdd(&g_ready[e * 64 + mb], 1);
        } else {
            // ================= DOWN TILE (fp16 2-term, R16 body) ============
            const int didx = idx - totalg;
            const int wm = wid >> 2, wn = wid & 3;
            int e = 0;
            while (didx >= s_offd[e + 1]) ++e;
            const int local = didx - s_offd[e];
            const int mb = local >> 3, nb = local & 7;
            const int ne = g_cnt[e];
            const int m0 = mb * 128, n0 = nb * 128;

            if (tid == 0) {
                const int* rp = &g_ready[e * 64 + mb];
                int v;
                do {
                    asm volatile("ld.global.acquire.gpu.b32 %0, [%1];" : "=r"(v) : "l"(rp));
                } while (v < 32);
            }
            __syncthreads();

            if (tid < 128) {
                int r  = m0 + tid;
                int rr = (r < ne) ? r : m0;
                s_pid[tid] = g_pid[e * NPAIR + rr];
                s_w[tid]   = g_wt [e * NPAIR + rr];
            }
            __syncthreads();

            const __half* gah = g_H16 + (size_t)s_pid[rA] * D_FFN + sg0 * 8;
            const size_t boff = ((size_t)e * D_MODEL + n0 + rA) * D_FFN + sg0 * 8;
            const __half* gbh = g_wdhi + boff;
            const __half* gbl = g_wdlo + boff;

            uint32_t aofs[4], bofs[2];
            #pragma unroll
            for (int i = 0; i < 4; ++i) {
                const int R = wm * 64 + i * 16 + (lane & 15);
                aofs[i] = swz((uint32_t)((R >> 1) * 128 + (R & 1) * 64) + klane);
            }
            #pragma unroll
            for (int j = 0; j < 2; ++j) {
                const int R = wn * 32 + j * 16 + (lane & 15);
                bofs[j] = swz((uint32_t)(8192 + (R >> 1) * 128 + (R & 1) * 64) + klane);
            }

#define DN_LOAD(kb, st) do {                                                    \
        const uint32_t db = sb + 2048 + (st) * ST_STAGE;                        \
        _Pragma("unroll") for (int j = 0; j < 2; ++j) {                         \
            CP_ASYNC(db + dA[j],          gah + (kb) + j * 8);                  \
            CP_ASYNC(db + dA[j] + 8192,   gbh + (kb) + j * 8);                  \
            CP_ASYNC(db + dA[j] + 16384,  gbl + (kb) + j * 8);                  \
        } } while (0)

            float acc[4][4][4];
            #pragma unroll
            for (int i = 0; i < 4; ++i)
                #pragma unroll
                for (int j = 0; j < 4; ++j)
                    #pragma unroll
                    for (int q = 0; q < 4; ++q) acc[i][j][q] = 0.f;

            const int NC = D_FFN / 32;
            DN_LOAD(0, 0);  CP_COMMIT();
            DN_LOAD(32, 1); CP_COMMIT();
            for (int ch = 0; ch < NC; ++ch) {
                if (ch == NC - 1) CP_WAIT(0); else CP_WAIT(1);
                __syncthreads();
                if (ch + 2 < NC) { DN_LOAD((ch + 2) * 32, (ch + 2) % 3); CP_COMMIT(); }
                const uint32_t base = sb + 2048 + (ch % 3) * ST_STAGE;
                #pragma unroll
                for (int s = 0; s < 2; ++s) {
                    const uint32_t sd = (uint32_t)(s * 32);
                    uint32_t ah[4][4];
                    #pragma unroll
                    for (int i = 0; i < 4; ++i)
                        ldsm4(ah[i], base + (aofs[i] ^ sd));
                    uint32_t bh[2][4], bl[2][4];
                    ldsm4(bh[0], base + (bofs[0] ^ sd));
                    ldsm4(bh[1], base + (bofs[1] ^ sd));
                    ldsm4(bl[0], base + (bofs[0] ^ sd ^ 24576u));
                    ldsm4(bl[1], base + (bofs[1] ^ sd ^ 24576u));
                    #pragma unroll
                    for (int i = 0; i < 4; ++i)
                        #pragma unroll
                        for (int j = 0; j < 2; ++j)
                            #pragma unroll
                            for (int h = 0; h < 2; ++h)
                                mma16816h(acc[i][j * 2 + h], ah[i], bh[j][h], bh[j][h + 2]);
                    #pragma unroll
                    for (int i = 0; i < 4; ++i)
                        #pragma unroll
                        for (int j = 0; j < 2; ++j)
                            #pragma unroll
                            for (int h = 0; h < 2; ++h)
                                mma16816h(acc[i][j * 2 + h], ah[i], bl[j][h], bl[j][h + 2]);
                }
            }
#undef DN_LOAD

            #pragma unroll
            for (int i = 0; i < 4; ++i) {
                const int m1 = wm * 64 + i * 16 + (lane >> 2);
                const int m2 = m1 + 8;
                const int pid1 = s_pid[m1], pid2 = s_pid[m2];
                const float w1 = s_w[m1], w2 = s_w[m2];
                #pragma unroll
                for (int jn = 0; jn < 4; ++jn) {
                    const int col = n0 + wn * 32 + jn * 8 + (lane & 3) * 2;
                    const float* c = acc[i][jn];
                    float2 v1 = { c[0] * w1, c[1] * w1 };
                    float2 v2 = { c[2] * w2, c[3] * w2 };
                    *(float2*)&g_Y[(size_t)pid1 * D_MODEL + col] = v1;
                    *(float2*)&g_Y[(size_t)pid2 * D_MODEL + col] = v2;
                }
            }
        }
    }
}

// ---------------- kernel: combine pairs + LayerNorm --------------------------
__global__ __launch_bounds__(256) void combine_ln_kernel(const float* __restrict__ gamma,
                                                         const float* __restrict__ beta,
                                                         float* __restrict__ out) {
    const int t   = blockIdx.x;
    const int tid = threadIdx.x;
    const float4 a = ((const float4*)(g_Y + (size_t)(2 * t)     * D_MODEL))[tid];
    const float4 b = ((const float4*)(g_Y + (size_t)(2 * t + 1) * D_MODEL))[tid];
    float4 v = { a.x + b.x, a.y + b.y, a.z + b.z, a.w + b.w };

    float s  = v.x + v.y + v.z + v.w;
    float sq = v.x * v.x + v.y * v.y + v.z * v.z + v.w * v.w;
    #pragma unroll
    for (int o = 16; o; o >>= 1) {
        s  += __shfl_xor_sync(0xffffffffu, s,  o);
        sq += __shfl_xor_sync(0xffffffffu, sq, o);
    }
    __shared__ float rs_[8], rq_[8];
    __shared__ float s_mu, s_rs;
    if ((tid & 31) == 0) { rs_[tid >> 5] = s; rq_[tid >> 5] = sq; }
    __syncthreads();
    if (tid == 0) {
        float S = 0.f, Q = 0.f;
        #pragma unroll
        for (int i = 0; i < 8; i++) { S += rs_[i]; Q += rq_[i]; }
        float mu  = S / (float)D_MODEL;
        float var = Q / (float)D_MODEL - mu * mu;
        s_mu = mu;
        s_rs = rsqrtf(var + 1e-5f);
    }
    __syncthreads();
    const float mu = s_mu, rs = s_rs;
    const float4 gg = ((const float4*)gamma)[tid];
    const float4 bb = ((const float4*)beta)[tid];
    float4 o;
    o.x = (v.x - mu) * rs * gg.x + bb.x;
    o.y = (v.y - mu) * rs * gg.y + bb.y;
    o.z = (v.z - mu) * rs * gg.z + bb.z;
    o.w = (v.w - mu) * rs * gg.w + bb.w;
    ((float4*)out)[(size_t)t * (D_MODEL / 4) + tid] = o;
}

// ---------------- launch ------------------------------------------------------
extern "C" void kernel_launch(void* const* d_in, const int* in_sizes, int n_in,
                              void* d_out, int out_size) {
    const float* x     = (const float*)d_in[0];
    const float* wr    = (const float*)d_in[1];
    const float* wg    = (const float*)d_in[2];
    const float* wu    = (const float*)d_in[3];
    const float* wd    = (const float*)d_in[4];
    const float* gamma = (const float*)d_in[5];
    const float* beta  = (const float*)d_in[6];
    float* out = (float*)d_out;

    cudaFuncSetAttribute(moe_fused_kernel, cudaFuncAttributeMaxDynamicSharedMemorySize, FU_SMEM);

    zero_cnt_kernel<<<1, 512>>>();
    router_kernel<<<T_TOKENS, 256>>>(x, wr);
    split_all_kernel<<<6656, 256>>>((const float4*)x, (const float4*)wg,
                                    (const float4*)wu, (const float4*)wd);
    moe_fused_kernel<<<304, 256, FU_SMEM>>>();
    combine_ln_kernel<<<T_TOKENS, 256>>>(gamma, beta, out);
}